// round 1
// baseline (speedup 1.0000x reference)
#include <cuda_runtime.h>

#define Bq 4
#define Sq 2048
#define Dq 1024
#define Hq 16
#define DKq 64
#define Mrows (Bq*Sq)
#define STRIDE 68   // smem row stride (floats) for 64-wide tiles, 16B-aligned padding

// Scratch (allocation-free rule: __device__ globals)
__device__ float g_q[Mrows*Dq];
__device__ float g_k[Mrows*Dq];
__device__ float g_v[Mrows*Dq];
__device__ float g_a[Mrows*Dq];

// ---------------------------------------------------------------------------
// C[M,N] = A[M,K] @ B[N,K]^T   (both row-major, K contiguous)
// 128x128 block, BK=16, 256 threads, 8x8 per-thread microtile.
// ---------------------------------------------------------------------------
__global__ void __launch_bounds__(256) gemm_nt(const float* __restrict__ A,
                                               const float* __restrict__ Bw,
                                               float* __restrict__ C,
                                               int M, int N, int K)
{
    __shared__ float As[16][132];
    __shared__ float Bs[16][132];
    const int tid = threadIdx.x;
    const int tx = tid & 15, ty = tid >> 4;
    const int bm = blockIdx.y * 128, bn = blockIdx.x * 128;
    const int lrow = tid >> 2;            // 0..63
    const int kq   = (tid & 3) << 2;      // 0,4,8,12

    float acc[8][8];
    #pragma unroll
    for (int i = 0; i < 8; ++i)
        #pragma unroll
        for (int j = 0; j < 8; ++j) acc[i][j] = 0.f;

    for (int k0 = 0; k0 < K; k0 += 16) {
        #pragma unroll
        for (int i = 0; i < 2; ++i) {
            int r = lrow + i * 64;
            float4 va = *reinterpret_cast<const float4*>(A  + (size_t)(bm + r) * K + k0 + kq);
            As[kq+0][r] = va.x; As[kq+1][r] = va.y; As[kq+2][r] = va.z; As[kq+3][r] = va.w;
            float4 vb = *reinterpret_cast<const float4*>(Bw + (size_t)(bn + r) * K + k0 + kq);
            Bs[kq+0][r] = vb.x; Bs[kq+1][r] = vb.y; Bs[kq+2][r] = vb.z; Bs[kq+3][r] = vb.w;
        }
        __syncthreads();
        #pragma unroll
        for (int kk = 0; kk < 16; ++kk) {
            float a[8], b[8];
            #pragma unroll
            for (int i = 0; i < 8; ++i) a[i] = As[kk][ty*8 + i];
            #pragma unroll
            for (int j = 0; j < 8; ++j) b[j] = Bs[kk][tx*8 + j];
            #pragma unroll
            for (int i = 0; i < 8; ++i)
                #pragma unroll
                for (int j = 0; j < 8; ++j) acc[i][j] += a[i] * b[j];
        }
        __syncthreads();
    }
    #pragma unroll
    for (int i = 0; i < 8; ++i) {
        size_t off = (size_t)(bm + ty*8 + i) * N + bn + tx*8;
        *reinterpret_cast<float4*>(C + off)     = make_float4(acc[i][0], acc[i][1], acc[i][2], acc[i][3]);
        *reinterpret_cast<float4*>(C + off + 4) = make_float4(acc[i][4], acc[i][5], acc[i][6], acc[i][7]);
    }
}

// ---------------------------------------------------------------------------
// Causal flash attention, fp32. One block = 64 query rows of one (b,h).
// 256 threads: thread = (row r = tid>>2, tx = tid&3).
// Score phase: thread owns keys j = tx + jj*4 (strided -> conflict-free K LDS).
// PV phase:    thread owns dims d = tx*16 + dd (blocked -> float4 V LDS).
// P handoff is within the 4-lane row group -> __syncwarp only.
// ---------------------------------------------------------------------------
extern __shared__ float smem[];
__global__ void __launch_bounds__(256, 2) attn_kernel(const float* __restrict__ Qg,
                                                      const float* __restrict__ Kg,
                                                      const float* __restrict__ Vg,
                                                      float* __restrict__ Og)
{
    float* Qs = smem;                  // 64*STRIDE
    float* Ks = Qs + 64*STRIDE;
    float* Vs = Ks + 64*STRIDE;
    float* Ps = Vs + 64*STRIDE;

    const int tid = threadIdx.x;
    const int r  = tid >> 2;           // query row in tile
    const int tx = tid & 3;
    const int qt = blockIdx.x;         // query tile
    const int bh = blockIdx.y;
    const int b = bh >> 4, h = bh & 15;
    const size_t base = (size_t)b * Sq * Dq + (size_t)h * DKq;
    const int q0 = qt * 64;
    const int qi = q0 + r;

    // Load Q tile, pre-scaled by 1/sqrt(64)
    #pragma unroll
    for (int i = 0; i < 4; ++i) {
        int id = tid + i * 256;
        int rr = id >> 4;
        int c4 = (id & 15) << 2;
        float4 v = *reinterpret_cast<const float4*>(Qg + base + (size_t)(q0 + rr) * Dq + c4);
        float* dst = Qs + rr*STRIDE + c4;
        dst[0] = v.x * 0.125f; dst[1] = v.y * 0.125f;
        dst[2] = v.z * 0.125f; dst[3] = v.w * 0.125f;
    }

    float m = -1e30f, l = 0.f;
    float o[16];
    #pragma unroll
    for (int i = 0; i < 16; ++i) o[i] = 0.f;

    for (int t = 0; t <= qt; ++t) {
        const int k0 = t * 64;
        // Load K,V tiles
        #pragma unroll
        for (int i = 0; i < 4; ++i) {
            int id = tid + i * 256;
            int rr = id >> 4;
            int c4 = (id & 15) << 2;
            size_t g = base + (size_t)(k0 + rr) * Dq + c4;
            *reinterpret_cast<float4*>(Ks + rr*STRIDE + c4) = *reinterpret_cast<const float4*>(Kg + g);
            *reinterpret_cast<float4*>(Vs + rr*STRIDE + c4) = *reinterpret_cast<const float4*>(Vg + g);
        }
        __syncthreads();

        // Scores for keys j = tx + jj*4
        float s[16];
        #pragma unroll
        for (int jj = 0; jj < 16; ++jj) s[jj] = 0.f;
        #pragma unroll
        for (int k = 0; k < 64; k += 4) {
            float4 q4 = *reinterpret_cast<const float4*>(Qs + r*STRIDE + k);
            #pragma unroll
            for (int jj = 0; jj < 16; ++jj) {
                float4 k4 = *reinterpret_cast<const float4*>(Ks + (tx + jj*4)*STRIDE + k);
                s[jj] += q4.x*k4.x + q4.y*k4.y + q4.z*k4.z + q4.w*k4.w;
            }
        }
        if (t == qt) {
            #pragma unroll
            for (int jj = 0; jj < 16; ++jj)
                if (tx + jj*4 > r) s[jj] = -1e30f;
        }

        // Online softmax (stats shared across the 4-lane row group)
        float tm = s[0];
        #pragma unroll
        for (int jj = 1; jj < 16; ++jj) tm = fmaxf(tm, s[jj]);
        tm = fmaxf(tm, __shfl_xor_sync(0xffffffffu, tm, 1));
        tm = fmaxf(tm, __shfl_xor_sync(0xffffffffu, tm, 2));
        float mn = fmaxf(m, tm);
        float c  = __expf(m - mn);
        float ts = 0.f;
        #pragma unroll
        for (int jj = 0; jj < 16; ++jj) {
            float p = __expf(s[jj] - mn);
            ts += p;
            Ps[r*STRIDE + tx + jj*4] = p;
        }
        ts += __shfl_xor_sync(0xffffffffu, ts, 1);
        ts += __shfl_xor_sync(0xffffffffu, ts, 2);
        l = l * c + ts;
        m = mn;
        #pragma unroll
        for (int i = 0; i < 16; ++i) o[i] *= c;
        __syncwarp();

        // PV accumulation: dims d = tx*16 + dd
        #pragma unroll 4
        for (int j = 0; j < 64; ++j) {
            float p = Ps[r*STRIDE + j];
            const float* vrow = Vs + j*STRIDE + tx*16;
            #pragma unroll
            for (int dd = 0; dd < 16; dd += 4) {
                float4 v4 = *reinterpret_cast<const float4*>(vrow + dd);
                o[dd+0] += p * v4.x; o[dd+1] += p * v4.y;
                o[dd+2] += p * v4.z; o[dd+3] += p * v4.w;
            }
        }
        __syncthreads();
    }

    float inv = 1.f / l;
    size_t go = base + (size_t)qi * Dq + tx*16;
    #pragma unroll
    for (int dd = 0; dd < 16; dd += 4)
        *reinterpret_cast<float4*>(Og + go + dd) =
            make_float4(o[dd]*inv, o[dd+1]*inv, o[dd+2]*inv, o[dd+3]*inv);
}

// ---------------------------------------------------------------------------
extern "C" void kernel_launch(void* const* d_in, const int* in_sizes, int n_in,
                              void* d_out, int out_size)
{
    const float* x  = (const float*)d_in[0];
    const float* wq = (const float*)d_in[1];
    const float* wk = (const float*)d_in[2];
    const float* wv = (const float*)d_in[3];
    const float* wo = (const float*)d_in[4];
    float* out = (float*)d_out;

    float *q, *k, *v, *a;
    cudaGetSymbolAddress((void**)&q, g_q);
    cudaGetSymbolAddress((void**)&k, g_k);
    cudaGetSymbolAddress((void**)&v, g_v);
    cudaGetSymbolAddress((void**)&a, g_a);

    dim3 gg(Dq/128, Mrows/128);
    gemm_nt<<<gg, 256>>>(x, wq, q, Mrows, Dq, Dq);
    gemm_nt<<<gg, 256>>>(x, wk, k, Mrows, Dq, Dq);
    gemm_nt<<<gg, 256>>>(x, wv, v, Mrows, Dq, Dq);

    int smem_bytes = 4 * 64 * STRIDE * sizeof(float);   // 69632 B
    cudaFuncSetAttribute(attn_kernel, cudaFuncAttributeMaxDynamicSharedMemorySize, smem_bytes);
    attn_kernel<<<dim3(Sq/64, Bq*Hq), 256, smem_bytes>>>(q, k, v, a);

    gemm_nt<<<gg, 256>>>(a, wo, out, Mrows, Dq, Dq);
}

// round 2
// speedup vs baseline: 1.3502x; 1.3502x over previous
#include <cuda_runtime.h>
#include <cstdint>
#include <cstddef>

#define Bq 4
#define Sq 2048
#define Dq 1024
#define Hq 16
#define DKq 64
#define Mrows (Bq*Sq)
#define STRIDE 68   // smem row stride (floats) for attention 64-wide tiles

// Scratch (allocation-free rule: __device__ globals)
__device__ float g_q[Mrows*Dq];
__device__ float g_k[Mrows*Dq];
__device__ float g_v[Mrows*Dq];
__device__ float g_a[Mrows*Dq];

__device__ __forceinline__ uint32_t f2tf(float f) {
    uint32_t u;
    asm("cvt.rna.tf32.f32 %0, %1;" : "=r"(u) : "f"(f));
    return u;
}

__device__ __forceinline__ void mma_tf32(float* c, uint4 a, uint32_t b0, uint32_t b1) {
    asm volatile("mma.sync.aligned.m16n8k8.row.col.f32.tf32.tf32.f32 "
        "{%0,%1,%2,%3}, {%4,%5,%6,%7}, {%8,%9}, {%0,%1,%2,%3};"
        : "+f"(c[0]), "+f"(c[1]), "+f"(c[2]), "+f"(c[3])
        : "r"(a.x), "r"(a.y), "r"(a.z), "r"(a.w), "r"(b0), "r"(b1));
}

// ---------------------------------------------------------------------------
// TF32 tensor-core GEMM: C[M,N] = A[M,K] @ W[N,K]^T (row-major, K contiguous)
// BM=128, BN=64, BK=32. 256 threads = 8 warps in 4(m) x 2(n); warp tile 32x32.
// Smem tiles stored in MMA FRAGMENT ORDER:
//   As[buf][mt(8)][ks(4)][lane(32)^swz][word(4)]  word = {a0,a1,a2,a3}
//   Bs[buf][ntp(4)][ks(4)][lane(32)^swz][word(4)] word = {b0_lo,b1_lo,b0_hi,b1_hi}
// so a full A fragment = one lds.128; two packed B fragments = one lds.128.
// Lane-swizzle: lane ^ (ks<<1) makes the scatter STS bank-conflict-free while
// keeping the fragment lds.128 a pure permutation (conflict-free).
// ---------------------------------------------------------------------------
__global__ void __launch_bounds__(256) gemm_tf32(const float* __restrict__ A,
                                                const float* __restrict__ W,
                                                float* __restrict__ C,
                                                int M, int N, int K)
{
    __shared__ uint32_t As[2][4096];  // 16KB each
    __shared__ uint32_t Bs[2][2048];  // 8KB each

    const int tid  = threadIdx.x;
    const int lane = tid & 31, wid = tid >> 5;
    const int wm = wid >> 1, wn = wid & 1;      // warp grid 4x2
    const int g = lane >> 2, t = lane & 3;
    const int bm = blockIdx.y * 128, bn = blockIdx.x * 64;

    const float* Ab = A + (size_t)bm * K;
    const float* Wb = W + (size_t)bn * K;

    const int rbase = tid >> 3;          // 0..31
    const int kc    = (tid & 7) << 2;    // 0,4,..,28 within chunk
    const int ks_   = (tid & 7) >> 1;    // k8 step of this thread's float4
    const int hi_   = tid & 1;           // upper half of k8 (cols 4-7)?

    float4 a_st[4], b_st[2];

    float acc[2][4][4];
    #pragma unroll
    for (int mt = 0; mt < 2; ++mt)
        #pragma unroll
        for (int j = 0; j < 4; ++j)
            #pragma unroll
            for (int e = 0; e < 4; ++e) acc[mt][j][e] = 0.f;

    const int nch = K >> 5;

    // ---- stage chunk 0 ----
    #pragma unroll
    for (int i = 0; i < 4; ++i)
        a_st[i] = *reinterpret_cast<const float4*>(Ab + (size_t)(rbase + 32*i) * K + kc);
    #pragma unroll
    for (int i = 0; i < 2; ++i)
        b_st[i] = *reinterpret_cast<const float4*>(Wb + (size_t)(rbase + 32*i) * K + kc);

    // scatter-store helper expanded inline (buf 0)
    {
        #pragma unroll
        for (int i = 0; i < 4; ++i) {
            int r = rbase + 32*i;
            int mt = r >> 4, rr = r & 15;
            int w  = (rr >> 3) + (hi_ << 1);
            int base = (mt*4 + ks_) * 32;
            int l0 = (rr & 7) << 2;
            const float* f = &a_st[i].x;
            #pragma unroll
            for (int j = 0; j < 4; ++j)
                As[0][(base + ((l0 + j) ^ (ks_ << 1))) * 4 + w] = f2tf(f[j]);
        }
        #pragma unroll
        for (int i = 0; i < 2; ++i) {
            int n = rbase + 32*i;
            int nt = n >> 3, gg = n & 7;
            int w  = ((nt & 1) << 1) + hi_;
            int base = ((nt >> 1)*4 + ks_) * 32;
            int l0 = gg << 2;
            const float* f = &b_st[i].x;
            #pragma unroll
            for (int j = 0; j < 4; ++j)
                Bs[0][(base + ((l0 + j) ^ (ks_ << 1))) * 4 + w] = f2tf(f[j]);
        }
    }
    __syncthreads();

    for (int ch = 0; ch < nch; ++ch) {
        const int buf = ch & 1;

        // prefetch next chunk into registers
        if (ch + 1 < nch) {
            const int kc0 = (ch + 1) << 5;
            #pragma unroll
            for (int i = 0; i < 4; ++i)
                a_st[i] = *reinterpret_cast<const float4*>(Ab + (size_t)(rbase + 32*i) * K + kc0 + kc);
            #pragma unroll
            for (int i = 0; i < 2; ++i)
                b_st[i] = *reinterpret_cast<const float4*>(Wb + (size_t)(rbase + 32*i) * K + kc0 + kc);
        }

        // compute 4 k8 steps on current buffer
        #pragma unroll
        for (int ks = 0; ks < 4; ++ks) {
            uint4 af[2], bf[2];
            const int sl = lane ^ (ks << 1);
            #pragma unroll
            for (int mt = 0; mt < 2; ++mt)
                af[mt] = *reinterpret_cast<const uint4*>(
                    &As[buf][(((wm*2 + mt)*4 + ks)*32 + sl) * 4]);
            #pragma unroll
            for (int p = 0; p < 2; ++p)
                bf[p] = *reinterpret_cast<const uint4*>(
                    &Bs[buf][(((wn*2 + p)*4 + ks)*32 + sl) * 4]);
            #pragma unroll
            for (int mt = 0; mt < 2; ++mt) {
                mma_tf32(acc[mt][0], af[mt], bf[0].x, bf[0].y);
                mma_tf32(acc[mt][1], af[mt], bf[0].z, bf[0].w);
                mma_tf32(acc[mt][2], af[mt], bf[1].x, bf[1].y);
                mma_tf32(acc[mt][3], af[mt], bf[1].z, bf[1].w);
            }
        }

        // store prefetched chunk into other buffer
        if (ch + 1 < nch) {
            const int nb = buf ^ 1;
            #pragma unroll
            for (int i = 0; i < 4; ++i) {
                int r = rbase + 32*i;
                int mt = r >> 4, rr = r & 15;
                int w  = (rr >> 3) + (hi_ << 1);
                int base = (mt*4 + ks_) * 32;
                int l0 = (rr & 7) << 2;
                const float* f = &a_st[i].x;
                #pragma unroll
                for (int j = 0; j < 4; ++j)
                    As[nb][(base + ((l0 + j) ^ (ks_ << 1))) * 4 + w] = f2tf(f[j]);
            }
            #pragma unroll
            for (int i = 0; i < 2; ++i) {
                int n = rbase + 32*i;
                int nt = n >> 3, gg = n & 7;
                int w  = ((nt & 1) << 1) + hi_;
                int base = ((nt >> 1)*4 + ks_) * 32;
                int l0 = gg << 2;
                const float* f = &b_st[i].x;
                #pragma unroll
                for (int j = 0; j < 4; ++j)
                    Bs[nb][(base + ((l0 + j) ^ (ks_ << 1))) * 4 + w] = f2tf(f[j]);
            }
        }
        __syncthreads();
    }

    // epilogue
    #pragma unroll
    for (int mt = 0; mt < 2; ++mt) {
        #pragma unroll
        for (int j = 0; j < 4; ++j) {
            int m = bm + wm*32 + mt*16 + g;
            int n = bn + wn*32 + j*8 + t*2;
            float2 v0 = make_float2(acc[mt][j][0], acc[mt][j][1]);
            float2 v1 = make_float2(acc[mt][j][2], acc[mt][j][3]);
            *reinterpret_cast<float2*>(C + (size_t)m * N + n)       = v0;
            *reinterpret_cast<float2*>(C + (size_t)(m + 8) * N + n) = v1;
        }
    }
}

// ---------------------------------------------------------------------------
// Causal flash attention, fp32 (unchanged from R1).
// ---------------------------------------------------------------------------
extern __shared__ float smem[];
__global__ void __launch_bounds__(256, 2) attn_kernel(const float* __restrict__ Qg,
                                                      const float* __restrict__ Kg,
                                                      const float* __restrict__ Vg,
                                                      float* __restrict__ Og)
{
    float* Qs = smem;
    float* Ks = Qs + 64*STRIDE;
    float* Vs = Ks + 64*STRIDE;
    float* Ps = Vs + 64*STRIDE;

    const int tid = threadIdx.x;
    const int r  = tid >> 2;
    const int tx = tid & 3;
    const int qt = blockIdx.x;
    const int bh = blockIdx.y;
    const int b = bh >> 4, h = bh & 15;
    const size_t base = (size_t)b * Sq * Dq + (size_t)h * DKq;
    const int q0 = qt * 64;
    const int qi = q0 + r;

    #pragma unroll
    for (int i = 0; i < 4; ++i) {
        int id = tid + i * 256;
        int rr = id >> 4;
        int c4 = (id & 15) << 2;
        float4 v = *reinterpret_cast<const float4*>(Qg + base + (size_t)(q0 + rr) * Dq + c4);
        float* dst = Qs + rr*STRIDE + c4;
        dst[0] = v.x * 0.125f; dst[1] = v.y * 0.125f;
        dst[2] = v.z * 0.125f; dst[3] = v.w * 0.125f;
    }

    float m = -1e30f, l = 0.f;
    float o[16];
    #pragma unroll
    for (int i = 0; i < 16; ++i) o[i] = 0.f;

    for (int t = 0; t <= qt; ++t) {
        const int k0 = t * 64;
        #pragma unroll
        for (int i = 0; i < 4; ++i) {
            int id = tid + i * 256;
            int rr = id >> 4;
            int c4 = (id & 15) << 2;
            size_t gg = base + (size_t)(k0 + rr) * Dq + c4;
            *reinterpret_cast<float4*>(Ks + rr*STRIDE + c4) = *reinterpret_cast<const float4*>(Kg + gg);
            *reinterpret_cast<float4*>(Vs + rr*STRIDE + c4) = *reinterpret_cast<const float4*>(Vg + gg);
        }
        __syncthreads();

        float s[16];
        #pragma unroll
        for (int jj = 0; jj < 16; ++jj) s[jj] = 0.f;
        #pragma unroll
        for (int k = 0; k < 64; k += 4) {
            float4 q4 = *reinterpret_cast<const float4*>(Qs + r*STRIDE + k);
            #pragma unroll
            for (int jj = 0; jj < 16; ++jj) {
                float4 k4 = *reinterpret_cast<const float4*>(Ks + (tx + jj*4)*STRIDE + k);
                s[jj] += q4.x*k4.x + q4.y*k4.y + q4.z*k4.z + q4.w*k4.w;
            }
        }
        if (t == qt) {
            #pragma unroll
            for (int jj = 0; jj < 16; ++jj)
                if (tx + jj*4 > r) s[jj] = -1e30f;
        }

        float tm = s[0];
        #pragma unroll
        for (int jj = 1; jj < 16; ++jj) tm = fmaxf(tm, s[jj]);
        tm = fmaxf(tm, __shfl_xor_sync(0xffffffffu, tm, 1));
        tm = fmaxf(tm, __shfl_xor_sync(0xffffffffu, tm, 2));
        float mn = fmaxf(m, tm);
        float c  = __expf(m - mn);
        float ts = 0.f;
        #pragma unroll
        for (int jj = 0; jj < 16; ++jj) {
            float p = __expf(s[jj] - mn);
            ts += p;
            Ps[r*STRIDE + tx + jj*4] = p;
        }
        ts += __shfl_xor_sync(0xffffffffu, ts, 1);
        ts += __shfl_xor_sync(0xffffffffu, ts, 2);
        l = l * c + ts;
        m = mn;
        #pragma unroll
        for (int i = 0; i < 16; ++i) o[i] *= c;
        __syncwarp();

        #pragma unroll 4
        for (int j = 0; j < 64; ++j) {
            float p = Ps[r*STRIDE + j];
            const float* vrow = Vs + j*STRIDE + tx*16;
            #pragma unroll
            for (int dd = 0; dd < 16; dd += 4) {
                float4 v4 = *reinterpret_cast<const float4*>(vrow + dd);
                o[dd+0] += p * v4.x; o[dd+1] += p * v4.y;
                o[dd+2] += p * v4.z; o[dd+3] += p * v4.w;
            }
        }
        __syncthreads();
    }

    float inv = 1.f / l;
    size_t go = base + (size_t)qi * Dq + tx*16;
    #pragma unroll
    for (int dd = 0; dd < 16; dd += 4)
        *reinterpret_cast<float4*>(Og + go + dd) =
            make_float4(o[dd]*inv, o[dd+1]*inv, o[dd+2]*inv, o[dd+3]*inv);
}

// ---------------------------------------------------------------------------
extern "C" void kernel_launch(void* const* d_in, const int* in_sizes, int n_in,
                              void* d_out, int out_size)
{
    const float* x  = (const float*)d_in[0];
    const float* wq = (const float*)d_in[1];
    const float* wk = (const float*)d_in[2];
    const float* wv = (const float*)d_in[3];
    const float* wo = (const float*)d_in[4];
    float* out = (float*)d_out;

    float *q, *k, *v, *a;
    cudaGetSymbolAddress((void**)&q, g_q);
    cudaGetSymbolAddress((void**)&k, g_k);
    cudaGetSymbolAddress((void**)&v, g_v);
    cudaGetSymbolAddress((void**)&a, g_a);

    dim3 gg(Dq/64, Mrows/128);   // (16, 64)
    gemm_tf32<<<gg, 256>>>(x, wq, q, Mrows, Dq, Dq);
    gemm_tf32<<<gg, 256>>>(x, wk, k, Mrows, Dq, Dq);
    gemm_tf32<<<gg, 256>>>(x, wv, v, Mrows, Dq, Dq);

    int smem_bytes = 4 * 64 * STRIDE * sizeof(float);   // 69632 B
    cudaFuncSetAttribute(attn_kernel, cudaFuncAttributeMaxDynamicSharedMemorySize, smem_bytes);
    attn_kernel<<<dim3(Sq/64, Bq*Hq), 256, smem_bytes>>>(q, k, v, a);

    gemm_tf32<<<gg, 256>>>(a, wo, out, Mrows, Dq, Dq);
}

// round 4
// speedup vs baseline: 3.7450x; 2.7736x over previous
#include <cuda_runtime.h>
#include <cstdint>
#include <cstddef>

#define Bq 4
#define Sq 2048
#define Dq 1024
#define Hq 16
#define DKq 64
#define Mrows (Bq*Sq)
#define LNEG -1e30f

// Scratch (allocation-free rule: __device__ globals)
__device__ float g_q[Mrows*Dq];
__device__ float g_k[Mrows*Dq];
__device__ float g_v[Mrows*Dq];
__device__ float g_a[Mrows*Dq];

__device__ __forceinline__ uint32_t f2tf(float f) {
    uint32_t u;
    asm("cvt.rna.tf32.f32 %0, %1;" : "=r"(u) : "f"(f));
    return u;
}

__device__ __forceinline__ void mma_tf32(float* c, uint4 a, uint32_t b0, uint32_t b1) {
    asm volatile("mma.sync.aligned.m16n8k8.row.col.f32.tf32.tf32.f32 "
        "{%0,%1,%2,%3}, {%4,%5,%6,%7}, {%8,%9}, {%0,%1,%2,%3};"
        : "+f"(c[0]), "+f"(c[1]), "+f"(c[2]), "+f"(c[3])
        : "r"(a.x), "r"(a.y), "r"(a.z), "r"(a.w), "r"(b0), "r"(b1));
}

// ---------------------------------------------------------------------------
// TF32 tensor-core GEMM (unchanged): C[M,N] = A[M,K] @ W[N,K]^T
// ---------------------------------------------------------------------------
__global__ void __launch_bounds__(256) gemm_tf32(const float* __restrict__ A,
                                                const float* __restrict__ W,
                                                float* __restrict__ C,
                                                int M, int N, int K)
{
    __shared__ uint32_t As[2][4096];
    __shared__ uint32_t Bs[2][2048];

    const int tid  = threadIdx.x;
    const int lane = tid & 31, wid = tid >> 5;
    const int wm = wid >> 1, wn = wid & 1;
    const int g = lane >> 2, t = lane & 3;
    const int bm = blockIdx.y * 128, bn = blockIdx.x * 64;

    const float* Ab = A + (size_t)bm * K;
    const float* Wb = W + (size_t)bn * K;

    const int rbase = tid >> 3;
    const int kc    = (tid & 7) << 2;
    const int ks_   = (tid & 7) >> 1;
    const int hi_   = tid & 1;

    float4 a_st[4], b_st[2];
    float acc[2][4][4];
    #pragma unroll
    for (int mt = 0; mt < 2; ++mt)
        #pragma unroll
        for (int j = 0; j < 4; ++j)
            #pragma unroll
            for (int e = 0; e < 4; ++e) acc[mt][j][e] = 0.f;

    const int nch = K >> 5;

    #pragma unroll
    for (int i = 0; i < 4; ++i)
        a_st[i] = *reinterpret_cast<const float4*>(Ab + (size_t)(rbase + 32*i) * K + kc);
    #pragma unroll
    for (int i = 0; i < 2; ++i)
        b_st[i] = *reinterpret_cast<const float4*>(Wb + (size_t)(rbase + 32*i) * K + kc);

    {
        #pragma unroll
        for (int i = 0; i < 4; ++i) {
            int r = rbase + 32*i;
            int mt = r >> 4, rr = r & 15;
            int w  = (rr >> 3) + (hi_ << 1);
            int base = (mt*4 + ks_) * 32;
            int l0 = (rr & 7) << 2;
            const float* f = &a_st[i].x;
            #pragma unroll
            for (int j = 0; j < 4; ++j)
                As[0][(base + ((l0 + j) ^ (ks_ << 1))) * 4 + w] = f2tf(f[j]);
        }
        #pragma unroll
        for (int i = 0; i < 2; ++i) {
            int n = rbase + 32*i;
            int nt = n >> 3, gg = n & 7;
            int w  = ((nt & 1) << 1) + hi_;
            int base = ((nt >> 1)*4 + ks_) * 32;
            int l0 = gg << 2;
            const float* f = &b_st[i].x;
            #pragma unroll
            for (int j = 0; j < 4; ++j)
                Bs[0][(base + ((l0 + j) ^ (ks_ << 1))) * 4 + w] = f2tf(f[j]);
        }
    }
    __syncthreads();

    for (int ch = 0; ch < nch; ++ch) {
        const int buf = ch & 1;
        if (ch + 1 < nch) {
            const int kc0 = (ch + 1) << 5;
            #pragma unroll
            for (int i = 0; i < 4; ++i)
                a_st[i] = *reinterpret_cast<const float4*>(Ab + (size_t)(rbase + 32*i) * K + kc0 + kc);
            #pragma unroll
            for (int i = 0; i < 2; ++i)
                b_st[i] = *reinterpret_cast<const float4*>(Wb + (size_t)(rbase + 32*i) * K + kc0 + kc);
        }
        #pragma unroll
        for (int ks = 0; ks < 4; ++ks) {
            uint4 af[2], bf[2];
            const int sl = lane ^ (ks << 1);
            #pragma unroll
            for (int mt = 0; mt < 2; ++mt)
                af[mt] = *reinterpret_cast<const uint4*>(
                    &As[buf][(((wm*2 + mt)*4 + ks)*32 + sl) * 4]);
            #pragma unroll
            for (int p = 0; p < 2; ++p)
                bf[p] = *reinterpret_cast<const uint4*>(
                    &Bs[buf][(((wn*2 + p)*4 + ks)*32 + sl) * 4]);
            #pragma unroll
            for (int mt = 0; mt < 2; ++mt) {
                mma_tf32(acc[mt][0], af[mt], bf[0].x, bf[0].y);
                mma_tf32(acc[mt][1], af[mt], bf[0].z, bf[0].w);
                mma_tf32(acc[mt][2], af[mt], bf[1].x, bf[1].y);
                mma_tf32(acc[mt][3], af[mt], bf[1].z, bf[1].w);
            }
        }
        if (ch + 1 < nch) {
            const int nb = buf ^ 1;
            #pragma unroll
            for (int i = 0; i < 4; ++i) {
                int r = rbase + 32*i;
                int mt = r >> 4, rr = r & 15;
                int w  = (rr >> 3) + (hi_ << 1);
                int base = (mt*4 + ks_) * 32;
                int l0 = (rr & 7) << 2;
                const float* f = &a_st[i].x;
                #pragma unroll
                for (int j = 0; j < 4; ++j)
                    As[nb][(base + ((l0 + j) ^ (ks_ << 1))) * 4 + w] = f2tf(f[j]);
            }
            #pragma unroll
            for (int i = 0; i < 2; ++i) {
                int n = rbase + 32*i;
                int nt = n >> 3, gg = n & 7;
                int w  = ((nt & 1) << 1) + hi_;
                int base = ((nt >> 1)*4 + ks_) * 32;
                int l0 = gg << 2;
                const float* f = &b_st[i].x;
                #pragma unroll
                for (int j = 0; j < 4; ++j)
                    Bs[nb][(base + ((l0 + j) ^ (ks_ << 1))) * 4 + w] = f2tf(f[j]);
            }
        }
        __syncthreads();
    }

    #pragma unroll
    for (int mt = 0; mt < 2; ++mt) {
        #pragma unroll
        for (int j = 0; j < 4; ++j) {
            int m = bm + wm*32 + mt*16 + g;
            int n = bn + wn*32 + j*8 + t*2;
            *reinterpret_cast<float2*>(C + (size_t)m * N + n)       = make_float2(acc[mt][j][0], acc[mt][j][1]);
            *reinterpret_cast<float2*>(C + (size_t)(m + 8) * N + n) = make_float2(acc[mt][j][2], acc[mt][j][3]);
        }
    }
}

// ---------------------------------------------------------------------------
// Tensor-core causal flash attention (R3 design + epilogue l-reduction fix).
// Block = 128 q-rows of one (b,h). 8 warps, each owns an m16 slab, full n=64.
// K/V split into TF32 hi+lo (error only from Q/P single-rounding).
// lst0/lst1 are PER-LANE partial sums (consistently scaled because m is
// row-uniform); reduced across the 4 t-lanes once in the epilogue.
// ---------------------------------------------------------------------------
extern __shared__ uint32_t sm_u[];
__global__ void __launch_bounds__(256) attn_tc(const float* __restrict__ Qg,
                                               const float* __restrict__ Kg,
                                               const float* __restrict__ Vg,
                                               float* __restrict__ Og)
{
    uint4* QA = reinterpret_cast<uint4*>(sm_u);            // 2048 u4
    uint4* KB = reinterpret_cast<uint4*>(sm_u + 8192);     // 2048 u4
    uint4* VB = reinterpret_cast<uint4*>(sm_u + 16384);    // 2048 u4
    uint4* PA = reinterpret_cast<uint4*>(sm_u + 24576);    // 2048 u4 (aliases V stage)
    float* Vst = reinterpret_cast<float*>(sm_u + 24576);   // 64 x 68 floats

    const int tid  = threadIdx.x;
    const int lane = tid & 31, w = tid >> 5;
    const int g = lane >> 2, t = lane & 3;
    const int qb = 15 - blockIdx.x;          // heavy blocks first
    const int bh = blockIdx.y;
    const int b = bh >> 4, h = bh & 15;
    const size_t base = (size_t)b * Sq * Dq + (size_t)h * DKq;
    const int q0 = qb * 128;

    // ---- Build QA once (pre-scaled by 1/8, TF32) ----
    #pragma unroll
    for (int i = 0; i < 2; ++i) {
        int ta = tid + (i << 8);
        int kk = ta & 7, gg = (ta >> 3) & 7, sl = ta >> 6;
        int row = q0 + sl*16 + gg;
        const float* p0 = Qg + base + (size_t)row * Dq + kk*8;
        const float* p1 = p0 + 8*Dq;
        float4 a0 = *reinterpret_cast<const float4*>(p0);
        float4 a1 = *reinterpret_cast<const float4*>(p0 + 4);
        float4 b0 = *reinterpret_cast<const float4*>(p1);
        float4 b1 = *reinterpret_cast<const float4*>(p1 + 4);
        const float* fa0 = &a0.x; const float* fa1 = &a1.x;
        const float* fb0 = &b0.x; const float* fb1 = &b1.x;
        #pragma unroll
        for (int tt = 0; tt < 4; ++tt) {
            QA[sl*256 + gg*32 + 4*(kk ^ gg) + tt] =
                make_uint4(f2tf(fa0[tt]*0.125f), f2tf(fb0[tt]*0.125f),
                           f2tf(fa1[tt]*0.125f), f2tf(fb1[tt]*0.125f));
        }
    }

    const int row_hi = q0 + w*16 + 15;
    float mst0 = LNEG, mst1 = LNEG, lst0 = 0.f, lst1 = 0.f;
    float Od[8][4];
    #pragma unroll
    for (int n8 = 0; n8 < 8; ++n8)
        #pragma unroll
        for (int e = 0; e < 4; ++e) Od[n8][e] = 0.f;

    const int jmax = 2*qb + 1;
    for (int j = 0; j <= jmax; ++j) {
        const int key0 = j << 6;
        __syncthreads();                       // prior-tile smem reads done

        // K -> KB (hi/lo split, fragment-packed)
        #pragma unroll
        for (int i = 0; i < 2; ++i) {
            int ta = tid + (i << 8);
            int kk = ta & 7, key = ta >> 3;
            const float* kp = Kg + base + (size_t)(key0 + key) * Dq + kk*8;
            float4 f0 = *reinterpret_cast<const float4*>(kp);
            float4 f1 = *reinterpret_cast<const float4*>(kp + 4);
            const float* p0 = &f0.x; const float* p1 = &f1.x;
            int sw = 4*(kk ^ (key & 7));
            int txor = (key >> 3) & 3;
            #pragma unroll
            for (int tt = 0; tt < 4; ++tt) {
                uint32_t h0 = f2tf(p0[tt]);
                uint32_t l0 = f2tf(p0[tt] - __uint_as_float(h0));
                uint32_t h1 = f2tf(p1[tt]);
                uint32_t l1 = f2tf(p1[tt] - __uint_as_float(h1));
                KB[key*32 + sw + (tt ^ txor)] = make_uint4(h0, h1, l0, l1);
            }
        }
        // V raw -> stage (aliases P buffer; prior P reads already fenced)
        #pragma unroll
        for (int i = 0; i < 4; ++i) {
            int id = tid + (i << 8);
            int rr = id >> 4, c4 = (id & 15) << 2;
            *reinterpret_cast<float4*>(Vst + rr*68 + c4) =
                *reinterpret_cast<const float4*>(Vg + base + (size_t)(key0 + rr) * Dq + c4);
        }
        __syncthreads();

        // stage -> VB (transpose + hi/lo split)
        #pragma unroll
        for (int i = 0; i < 2; ++i) {
            int dk = tid & 63, kk = (tid >> 6) + (i << 2);
            float f[8];
            #pragma unroll
            for (int r = 0; r < 8; ++r) f[r] = Vst[(8*kk + r)*68 + dk];
            int sw = 4*(kk ^ (dk & 7));
            int txor = (dk >> 3) & 3;
            #pragma unroll
            for (int tt = 0; tt < 4; ++tt) {
                uint32_t h0 = f2tf(f[tt]);
                uint32_t l0 = f2tf(f[tt] - __uint_as_float(h0));
                uint32_t h1 = f2tf(f[tt+4]);
                uint32_t l1 = f2tf(f[tt+4] - __uint_as_float(h1));
                VB[dk*32 + sw + (tt ^ txor)] = make_uint4(h0, h1, l0, l1);
            }
        }
        __syncthreads();

        if (key0 <= row_hi) {
            // ---- QK^T ----
            float acc[8][4];
            #pragma unroll
            for (int n8 = 0; n8 < 8; ++n8)
                #pragma unroll
                for (int e = 0; e < 4; ++e) acc[n8][e] = 0.f;

            #pragma unroll
            for (int kk = 0; kk < 8; ++kk) {
                uint4 aq = QA[w*256 + g*32 + 4*(kk ^ g) + t];
                #pragma unroll
                for (int n8 = 0; n8 < 8; ++n8) {
                    uint4 kb = KB[(8*n8 + g)*32 + 4*(kk ^ g) + (t ^ (n8 & 3))];
                    mma_tf32(acc[n8], aq, kb.x, kb.y);
                    mma_tf32(acc[n8], aq, kb.z, kb.w);
                }
            }
            // ---- causal mask (only tiles that can clip) ----
            if (j >= 2*qb) {
                int r0 = q0 + w*16 + g, r1 = r0 + 8;
                #pragma unroll
                for (int n8 = 0; n8 < 8; ++n8) {
                    int c0 = key0 + 8*n8 + 2*t, c1 = c0 + 1;
                    if (c0 > r0) acc[n8][0] = LNEG;
                    if (c1 > r0) acc[n8][1] = LNEG;
                    if (c0 > r1) acc[n8][2] = LNEG;
                    if (c1 > r1) acc[n8][3] = LNEG;
                }
            }
            // ---- online softmax (rows g and g+8) ----
            float t0 = LNEG, t1 = LNEG;
            #pragma unroll
            for (int n8 = 0; n8 < 8; ++n8) {
                t0 = fmaxf(t0, fmaxf(acc[n8][0], acc[n8][1]));
                t1 = fmaxf(t1, fmaxf(acc[n8][2], acc[n8][3]));
            }
            t0 = fmaxf(t0, __shfl_xor_sync(0xffffffffu, t0, 1));
            t0 = fmaxf(t0, __shfl_xor_sync(0xffffffffu, t0, 2));
            t1 = fmaxf(t1, __shfl_xor_sync(0xffffffffu, t1, 1));
            t1 = fmaxf(t1, __shfl_xor_sync(0xffffffffu, t1, 2));
            float m0n = fmaxf(mst0, t0), m1n = fmaxf(mst1, t1);
            float c0 = __expf(mst0 - m0n), c1 = __expf(mst1 - m1n);
            float s0 = 0.f, s1 = 0.f;

            int d0 = 2*t, d1 = 2*t + 1;
            int tw0 = d0 & 3, sl0 = (d0 >> 2) << 1;
            int tw1 = d1 & 3, sl1 = (d1 >> 2) << 1;
            #pragma unroll
            for (int n8 = 0; n8 < 8; ++n8) {
                float p00 = __expf(acc[n8][0] - m0n);
                float p01 = __expf(acc[n8][1] - m0n);
                float p10 = __expf(acc[n8][2] - m1n);
                float p11 = __expf(acc[n8][3] - m1n);
                s0 += p00 + p01;
                s1 += p10 + p11;
                uint32_t* pw = reinterpret_cast<uint32_t*>(&PA[w*256 + g*32 + 4*(n8 ^ g)]);
                pw[tw0*4 + sl0]     = f2tf(p00);
                pw[tw0*4 + sl0 + 1] = f2tf(p10);
                pw[tw1*4 + sl1]     = f2tf(p01);
                pw[tw1*4 + sl1 + 1] = f2tf(p11);
            }
            lst0 = lst0 * c0 + s0;       // per-lane partial; c row-uniform
            lst1 = lst1 * c1 + s1;
            mst0 = m0n; mst1 = m1n;
            #pragma unroll
            for (int n8 = 0; n8 < 8; ++n8) {
                Od[n8][0] *= c0; Od[n8][1] *= c0;
                Od[n8][2] *= c1; Od[n8][3] *= c1;
            }
            __syncwarp();

            // ---- P @ V ----
            #pragma unroll
            for (int kk = 0; kk < 8; ++kk) {
                uint4 pa = PA[w*256 + g*32 + 4*(kk ^ g) + t];
                #pragma unroll
                for (int n8 = 0; n8 < 8; ++n8) {
                    uint4 vb = VB[(8*n8 + g)*32 + 4*(kk ^ g) + (t ^ (n8 & 3))];
                    mma_tf32(Od[n8], pa, vb.x, vb.y);
                    mma_tf32(Od[n8], pa, vb.z, vb.w);
                }
            }
        }
    }

    // ---- epilogue: reduce per-lane l partials across the 4 t-lanes ----
    lst0 += __shfl_xor_sync(0xffffffffu, lst0, 1);
    lst0 += __shfl_xor_sync(0xffffffffu, lst0, 2);
    lst1 += __shfl_xor_sync(0xffffffffu, lst1, 1);
    lst1 += __shfl_xor_sync(0xffffffffu, lst1, 2);
    float i0 = 1.f / lst0, i1 = 1.f / lst1;
    int r0 = q0 + w*16 + g;
    #pragma unroll
    for (int n8 = 0; n8 < 8; ++n8) {
        int col = h*64 + 8*n8 + 2*t;
        size_t o0 = (size_t)((size_t)b * Sq + r0) * Dq + col;
        *reinterpret_cast<float2*>(Og + o0)          = make_float2(Od[n8][0]*i0, Od[n8][1]*i0);
        *reinterpret_cast<float2*>(Og + o0 + 8*Dq)   = make_float2(Od[n8][2]*i1, Od[n8][3]*i1);
    }
}

// ---------------------------------------------------------------------------
extern "C" void kernel_launch(void* const* d_in, const int* in_sizes, int n_in,
                              void* d_out, int out_size)
{
    const float* x  = (const float*)d_in[0];
    const float* wq = (const float*)d_in[1];
    const float* wk = (const float*)d_in[2];
    const float* wv = (const float*)d_in[3];
    const float* wo = (const float*)d_in[4];
    float* out = (float*)d_out;

    float *q, *k, *v, *a;
    cudaGetSymbolAddress((void**)&q, g_q);
    cudaGetSymbolAddress((void**)&k, g_k);
    cudaGetSymbolAddress((void**)&v, g_v);
    cudaGetSymbolAddress((void**)&a, g_a);

    dim3 gg(Dq/64, Mrows/128);
    gemm_tf32<<<gg, 256>>>(x, wq, q, Mrows, Dq, Dq);
    gemm_tf32<<<gg, 256>>>(x, wk, k, Mrows, Dq, Dq);
    gemm_tf32<<<gg, 256>>>(x, wv, v, Mrows, Dq, Dq);

    int smem_attn = 131072;   // 4 x 32KB fragment-packed regions
    cudaFuncSetAttribute(attn_tc, cudaFuncAttributeMaxDynamicSharedMemorySize, smem_attn);
    attn_tc<<<dim3(16, Bq*Hq), 256, smem_attn>>>(q, k, v, a);

    gemm_tf32<<<gg, 256>>>(a, wo, out, Mrows, Dq, Dq);
}

// round 5
// speedup vs baseline: 4.3911x; 1.1725x over previous
#include <cuda_runtime.h>
#include <cstdint>
#include <cstddef>

#define Bq 4
#define Sq 2048
#define Dq 1024
#define Hq 16
#define DKq 64
#define Mrows (Bq*Sq)
#define NTILES 32          // key tiles per (b,h)
#define LNEG -1e30f

// Scratch (allocation-free rule: __device__ globals)
__device__ float g_q[Mrows*Dq];
__device__ float g_k[Mrows*Dq];
__device__ float g_v[Mrows*Dq];
__device__ float g_a[Mrows*Dq];
__device__ uint4 g_kp[(size_t)64*NTILES*2048];   // packed K fragments (hi+lo), 64MB
__device__ uint2 g_vp[(size_t)64*NTILES*2048];   // packed V fragments (hi only), 32MB

__device__ __forceinline__ uint32_t f2tf(float f) {
    uint32_t u;
    asm("cvt.rna.tf32.f32 %0, %1;" : "=r"(u) : "f"(f));
    return u;
}

__device__ __forceinline__ void mma_tf32(float* c, uint4 a, uint32_t b0, uint32_t b1) {
    asm volatile("mma.sync.aligned.m16n8k8.row.col.f32.tf32.tf32.f32 "
        "{%0,%1,%2,%3}, {%4,%5,%6,%7}, {%8,%9}, {%0,%1,%2,%3};"
        : "+f"(c[0]), "+f"(c[1]), "+f"(c[2]), "+f"(c[3])
        : "r"(a.x), "r"(a.y), "r"(a.z), "r"(a.w), "r"(b0), "r"(b1));
}

// ---------------------------------------------------------------------------
// TF32 tensor-core GEMM: C[M,N] = A[M,K] @ W[N,K]^T
// BM=128, BN=128, BK=32. 256 threads = 8 warps 4(m) x 2(n); warp tile 32x64.
// Fragment-packed smem (validated in R2/R4), 64KB dynamic, double-buffered.
// ---------------------------------------------------------------------------
extern __shared__ uint32_t gsm[];
__global__ void __launch_bounds__(256) gemm_tf32(const float* __restrict__ A,
                                                const float* __restrict__ W,
                                                float* __restrict__ C,
                                                int M, int N, int K)
{
    uint32_t (*As)[4096] = reinterpret_cast<uint32_t(*)[4096]>(gsm);          // 2 x 16KB
    uint32_t (*Bs)[4096] = reinterpret_cast<uint32_t(*)[4096]>(gsm + 8192);   // 2 x 16KB

    const int tid  = threadIdx.x;
    const int lane = tid & 31, wid = tid >> 5;
    const int wm = wid >> 1, wn = wid & 1;
    const int g = lane >> 2, t = lane & 3;
    const int bm = blockIdx.y * 128, bn = blockIdx.x * 128;

    const float* Ab = A + (size_t)bm * K;
    const float* Wb = W + (size_t)bn * K;

    const int rbase = tid >> 3;          // 0..31
    const int kc    = (tid & 7) << 2;
    const int ks_   = (tid & 7) >> 1;
    const int hi_   = tid & 1;

    float4 a_st[4], b_st[4];
    float acc[2][8][4];
    #pragma unroll
    for (int mt = 0; mt < 2; ++mt)
        #pragma unroll
        for (int j = 0; j < 8; ++j)
            #pragma unroll
            for (int e = 0; e < 4; ++e) acc[mt][j][e] = 0.f;

    const int nch = K >> 5;

    #pragma unroll
    for (int i = 0; i < 4; ++i) {
        a_st[i] = *reinterpret_cast<const float4*>(Ab + (size_t)(rbase + 32*i) * K + kc);
        b_st[i] = *reinterpret_cast<const float4*>(Wb + (size_t)(rbase + 32*i) * K + kc);
    }
    {
        #pragma unroll
        for (int i = 0; i < 4; ++i) {
            int r = rbase + 32*i;
            int mt = r >> 4, rr = r & 15;
            int w  = (rr >> 3) + (hi_ << 1);
            int base = (mt*4 + ks_) * 32;
            int l0 = (rr & 7) << 2;
            const float* f = &a_st[i].x;
            #pragma unroll
            for (int j = 0; j < 4; ++j)
                As[0][(base + ((l0 + j) ^ (ks_ << 1))) * 4 + w] = f2tf(f[j]);
        }
        #pragma unroll
        for (int i = 0; i < 4; ++i) {
            int n = rbase + 32*i;
            int nt = n >> 3, gg = n & 7;
            int w  = ((nt & 1) << 1) + hi_;
            int base = ((nt >> 1)*4 + ks_) * 32;
            int l0 = gg << 2;
            const float* f = &b_st[i].x;
            #pragma unroll
            for (int j = 0; j < 4; ++j)
                Bs[0][(base + ((l0 + j) ^ (ks_ << 1))) * 4 + w] = f2tf(f[j]);
        }
    }
    __syncthreads();

    for (int ch = 0; ch < nch; ++ch) {
        const int buf = ch & 1;
        if (ch + 1 < nch) {
            const int kc0 = (ch + 1) << 5;
            #pragma unroll
            for (int i = 0; i < 4; ++i) {
                a_st[i] = *reinterpret_cast<const float4*>(Ab + (size_t)(rbase + 32*i) * K + kc0 + kc);
                b_st[i] = *reinterpret_cast<const float4*>(Wb + (size_t)(rbase + 32*i) * K + kc0 + kc);
            }
        }
        #pragma unroll
        for (int ks = 0; ks < 4; ++ks) {
            uint4 af[2], bf[4];
            const int sl = lane ^ (ks << 1);
            #pragma unroll
            for (int mt = 0; mt < 2; ++mt)
                af[mt] = *reinterpret_cast<const uint4*>(
                    &As[buf][(((wm*2 + mt)*4 + ks)*32 + sl) * 4]);
            #pragma unroll
            for (int p = 0; p < 4; ++p)
                bf[p] = *reinterpret_cast<const uint4*>(
                    &Bs[buf][(((wn*4 + p)*4 + ks)*32 + sl) * 4]);
            #pragma unroll
            for (int mt = 0; mt < 2; ++mt)
                #pragma unroll
                for (int p = 0; p < 4; ++p) {
                    mma_tf32(acc[mt][2*p],   af[mt], bf[p].x, bf[p].y);
                    mma_tf32(acc[mt][2*p+1], af[mt], bf[p].z, bf[p].w);
                }
        }
        if (ch + 1 < nch) {
            const int nb = buf ^ 1;
            #pragma unroll
            for (int i = 0; i < 4; ++i) {
                int r = rbase + 32*i;
                int mt = r >> 4, rr = r & 15;
                int w  = (rr >> 3) + (hi_ << 1);
                int base = (mt*4 + ks_) * 32;
                int l0 = (rr & 7) << 2;
                const float* f = &a_st[i].x;
                #pragma unroll
                for (int j = 0; j < 4; ++j)
                    As[nb][(base + ((l0 + j) ^ (ks_ << 1))) * 4 + w] = f2tf(f[j]);
            }
            #pragma unroll
            for (int i = 0; i < 4; ++i) {
                int n = rbase + 32*i;
                int nt = n >> 3, gg = n & 7;
                int w  = ((nt & 1) << 1) + hi_;
                int base = ((nt >> 1)*4 + ks_) * 32;
                int l0 = gg << 2;
                const float* f = &b_st[i].x;
                #pragma unroll
                for (int j = 0; j < 4; ++j)
                    Bs[nb][(base + ((l0 + j) ^ (ks_ << 1))) * 4 + w] = f2tf(f[j]);
            }
        }
        __syncthreads();
    }

    #pragma unroll
    for (int mt = 0; mt < 2; ++mt) {
        #pragma unroll
        for (int j = 0; j < 8; ++j) {
            int m = bm + wm*32 + mt*16 + g;
            int n = bn + wn*64 + j*8 + t*2;
            *reinterpret_cast<float2*>(C + (size_t)m * N + n)       = make_float2(acc[mt][j][0], acc[mt][j][1]);
            *reinterpret_cast<float2*>(C + (size_t)(m + 8) * N + n) = make_float2(acc[mt][j][2], acc[mt][j][3]);
        }
    }
}

// ---------------------------------------------------------------------------
// Pack K (hi+lo) and V (hi, transposed) into mma-fragment order in gmem.
// Grid (NTILES, 64), 256 threads. Done ONCE per tile instead of per q-block.
// ---------------------------------------------------------------------------
__global__ void __launch_bounds__(256) pack_kv(const float* __restrict__ Kg,
                                               const float* __restrict__ Vg,
                                               uint4* __restrict__ kp,
                                               uint2* __restrict__ vp)
{
    __shared__ float Vst[64*68];
    const int j = blockIdx.x, bh = blockIdx.y;
    const int b = bh >> 4, h = bh & 15;
    const size_t base = (size_t)b * Sq * Dq + (size_t)h * DKq;
    const int key0 = j << 6;
    const int tid = threadIdx.x;
    uint4* kpt = kp + ((size_t)bh * NTILES + j) * 2048;
    uint2* vpt = vp + ((size_t)bh * NTILES + j) * 2048;

    // K -> hi/lo fragment-packed
    #pragma unroll
    for (int i = 0; i < 2; ++i) {
        int ta = tid + (i << 8);
        int kk = ta & 7, key = ta >> 3;
        const float* kq = Kg + base + (size_t)(key0 + key) * Dq + kk*8;
        float4 f0 = *reinterpret_cast<const float4*>(kq);
        float4 f1 = *reinterpret_cast<const float4*>(kq + 4);
        const float* p0 = &f0.x; const float* p1 = &f1.x;
        int sw = 4*(kk ^ (key & 7));
        int txor = (key >> 3) & 3;
        #pragma unroll
        for (int tt = 0; tt < 4; ++tt) {
            uint32_t h0 = f2tf(p0[tt]);
            uint32_t l0 = f2tf(p0[tt] - __uint_as_float(h0));
            uint32_t h1 = f2tf(p1[tt]);
            uint32_t l1 = f2tf(p1[tt] - __uint_as_float(h1));
            kpt[key*32 + sw + (tt ^ txor)] = make_uint4(h0, h1, l0, l1);
        }
    }
    // V -> stage
    #pragma unroll
    for (int i = 0; i < 4; ++i) {
        int id = tid + (i << 8);
        int rr = id >> 4, c4 = (id & 15) << 2;
        *reinterpret_cast<float4*>(Vst + rr*68 + c4) =
            *reinterpret_cast<const float4*>(Vg + base + (size_t)(key0 + rr) * Dq + c4);
    }
    __syncthreads();
    // stage -> transposed hi-only fragments
    #pragma unroll
    for (int i = 0; i < 2; ++i) {
        int dk = tid & 63, kk = (tid >> 6) + (i << 2);
        float f[8];
        #pragma unroll
        for (int r = 0; r < 8; ++r) f[r] = Vst[(8*kk + r)*68 + dk];
        int sw = 4*(kk ^ (dk & 7));
        int txor = (dk >> 3) & 3;
        #pragma unroll
        for (int tt = 0; tt < 4; ++tt)
            vpt[dk*32 + sw + (tt ^ txor)] = make_uint2(f2tf(f[tt]), f2tf(f[tt+4]));
    }
}

// ---------------------------------------------------------------------------
// Tensor-core causal flash attention, tiles streamed pre-packed from gmem.
// Block = 128 q-rows of one (b,h), 8 warps x m16, n=64 tiles.
// Smem: QA 32KB | KB 32KB | VB 16KB | PA 32KB = 112KB -> 2 CTAs/SM.
// __launch_bounds__(256,2) caps regs at 128 for the 2-CTA residency.
// ---------------------------------------------------------------------------
extern __shared__ uint32_t sm_u[];
__global__ void __launch_bounds__(256, 2) attn_tc(const float* __restrict__ Qg,
                                                  const uint4* __restrict__ kp,
                                                  const uint2* __restrict__ vp,
                                                  float* __restrict__ Og)
{
    uint4* QA = reinterpret_cast<uint4*>(sm_u);            // 2048 u4
    uint4* KB = reinterpret_cast<uint4*>(sm_u + 8192);     // 2048 u4
    uint2* VB = reinterpret_cast<uint2*>(sm_u + 16384);    // 2048 u2
    uint4* PA = reinterpret_cast<uint4*>(sm_u + 20480);    // 2048 u4

    const int tid  = threadIdx.x;
    const int lane = tid & 31, w = tid >> 5;
    const int g = lane >> 2, t = lane & 3;
    const int qb = 15 - blockIdx.x;          // heavy blocks first
    const int bh = blockIdx.y;
    const int b = bh >> 4, h = bh & 15;
    const size_t base = (size_t)b * Sq * Dq + (size_t)h * DKq;
    const int q0 = qb * 128;

    // ---- Build QA once (pre-scaled by 1/8, TF32) ----
    #pragma unroll
    for (int i = 0; i < 2; ++i) {
        int ta = tid + (i << 8);
        int kk = ta & 7, gg = (ta >> 3) & 7, sl = ta >> 6;
        int row = q0 + sl*16 + gg;
        const float* p0 = Qg + base + (size_t)row * Dq + kk*8;
        const float* p1 = p0 + 8*Dq;
        float4 a0 = *reinterpret_cast<const float4*>(p0);
        float4 a1 = *reinterpret_cast<const float4*>(p0 + 4);
        float4 b0 = *reinterpret_cast<const float4*>(p1);
        float4 b1 = *reinterpret_cast<const float4*>(p1 + 4);
        const float* fa0 = &a0.x; const float* fa1 = &a1.x;
        const float* fb0 = &b0.x; const float* fb1 = &b1.x;
        #pragma unroll
        for (int tt = 0; tt < 4; ++tt) {
            QA[sl*256 + gg*32 + 4*(kk ^ gg) + tt] =
                make_uint4(f2tf(fa0[tt]*0.125f), f2tf(fb0[tt]*0.125f),
                           f2tf(fa1[tt]*0.125f), f2tf(fb1[tt]*0.125f));
        }
    }

    const int row_hi = q0 + w*16 + 15;
    float mst0 = LNEG, mst1 = LNEG, lst0 = 0.f, lst1 = 0.f;
    float Od[8][4];
    #pragma unroll
    for (int n8 = 0; n8 < 8; ++n8)
        #pragma unroll
        for (int e = 0; e < 4; ++e) Od[n8][e] = 0.f;

    const int jmax = 2*qb + 1;
    for (int j = 0; j <= jmax; ++j) {
        const int key0 = j << 6;
        __syncthreads();                       // prior-tile smem reads done

        // Stream packed tiles gmem -> smem (pure copies, coalesced)
        const uint4* kpt = kp + ((size_t)bh * NTILES + j) * 2048;
        const uint2* vpt = vp + ((size_t)bh * NTILES + j) * 2048;
        #pragma unroll
        for (int i = 0; i < 8; ++i)
            KB[tid + (i << 8)] = kpt[tid + (i << 8)];
        #pragma unroll
        for (int i = 0; i < 8; ++i)
            VB[tid + (i << 8)] = vpt[tid + (i << 8)];
        __syncthreads();

        if (key0 <= row_hi) {
            // ---- QK^T (K hi+lo) ----
            float acc[8][4];
            #pragma unroll
            for (int n8 = 0; n8 < 8; ++n8)
                #pragma unroll
                for (int e = 0; e < 4; ++e) acc[n8][e] = 0.f;

            #pragma unroll
            for (int kk = 0; kk < 8; ++kk) {
                uint4 aq = QA[w*256 + g*32 + 4*(kk ^ g) + t];
                #pragma unroll
                for (int n8 = 0; n8 < 8; ++n8) {
                    uint4 kb = KB[(8*n8 + g)*32 + 4*(kk ^ g) + (t ^ (n8 & 3))];
                    mma_tf32(acc[n8], aq, kb.x, kb.y);
                    mma_tf32(acc[n8], aq, kb.z, kb.w);
                }
            }
            // ---- causal mask ----
            if (j >= 2*qb) {
                int r0 = q0 + w*16 + g, r1 = r0 + 8;
                #pragma unroll
                for (int n8 = 0; n8 < 8; ++n8) {
                    int c0 = key0 + 8*n8 + 2*t, c1 = c0 + 1;
                    if (c0 > r0) acc[n8][0] = LNEG;
                    if (c1 > r0) acc[n8][1] = LNEG;
                    if (c0 > r1) acc[n8][2] = LNEG;
                    if (c1 > r1) acc[n8][3] = LNEG;
                }
            }
            // ---- online softmax ----
            float t0 = LNEG, t1 = LNEG;
            #pragma unroll
            for (int n8 = 0; n8 < 8; ++n8) {
                t0 = fmaxf(t0, fmaxf(acc[n8][0], acc[n8][1]));
                t1 = fmaxf(t1, fmaxf(acc[n8][2], acc[n8][3]));
            }
            t0 = fmaxf(t0, __shfl_xor_sync(0xffffffffu, t0, 1));
            t0 = fmaxf(t0, __shfl_xor_sync(0xffffffffu, t0, 2));
            t1 = fmaxf(t1, __shfl_xor_sync(0xffffffffu, t1, 1));
            t1 = fmaxf(t1, __shfl_xor_sync(0xffffffffu, t1, 2));
            float m0n = fmaxf(mst0, t0), m1n = fmaxf(mst1, t1);
            float c0 = __expf(mst0 - m0n), c1 = __expf(mst1 - m1n);
            float s0 = 0.f, s1 = 0.f;

            int d0 = 2*t, d1 = 2*t + 1;
            int tw0 = d0 & 3, sl0 = (d0 >> 2) << 1;
            int tw1 = d1 & 3, sl1 = (d1 >> 2) << 1;
            #pragma unroll
            for (int n8 = 0; n8 < 8; ++n8) {
                float p00 = __expf(acc[n8][0] - m0n);
                float p01 = __expf(acc[n8][1] - m0n);
                float p10 = __expf(acc[n8][2] - m1n);
                float p11 = __expf(acc[n8][3] - m1n);
                s0 += p00 + p01;
                s1 += p10 + p11;
                uint32_t* pw = reinterpret_cast<uint32_t*>(&PA[w*256 + g*32 + 4*(n8 ^ g)]);
                pw[tw0*4 + sl0]     = f2tf(p00);
                pw[tw0*4 + sl0 + 1] = f2tf(p10);
                pw[tw1*4 + sl1]     = f2tf(p01);
                pw[tw1*4 + sl1 + 1] = f2tf(p11);
            }
            lst0 = lst0 * c0 + s0;       // per-lane partials; c row-uniform
            lst1 = lst1 * c1 + s1;
            mst0 = m0n; mst1 = m1n;
            #pragma unroll
            for (int n8 = 0; n8 < 8; ++n8) {
                Od[n8][0] *= c0; Od[n8][1] *= c0;
                Od[n8][2] *= c1; Od[n8][3] *= c1;
            }
            __syncwarp();

            // ---- P @ V (V hi only) ----
            #pragma unroll
            for (int kk = 0; kk < 8; ++kk) {
                uint4 pa = PA[w*256 + g*32 + 4*(kk ^ g) + t];
                #pragma unroll
                for (int n8 = 0; n8 < 8; ++n8) {
                    uint2 vb = VB[(8*n8 + g)*32 + 4*(kk ^ g) + (t ^ (n8 & 3))];
                    mma_tf32(Od[n8], pa, vb.x, vb.y);
                }
            }
        }
    }

    // ---- epilogue: reduce per-lane l partials across the 4 t-lanes ----
    lst0 += __shfl_xor_sync(0xffffffffu, lst0, 1);
    lst0 += __shfl_xor_sync(0xffffffffu, lst0, 2);
    lst1 += __shfl_xor_sync(0xffffffffu, lst1, 1);
    lst1 += __shfl_xor_sync(0xffffffffu, lst1, 2);
    float i0 = 1.f / lst0, i1 = 1.f / lst1;
    int r0 = q0 + w*16 + g;
    #pragma unroll
    for (int n8 = 0; n8 < 8; ++n8) {
        int col = h*64 + 8*n8 + 2*t;
        size_t o0 = (size_t)((size_t)b * Sq + r0) * Dq + col;
        *reinterpret_cast<float2*>(Og + o0)          = make_float2(Od[n8][0]*i0, Od[n8][1]*i0);
        *reinterpret_cast<float2*>(Og + o0 + 8*Dq)   = make_float2(Od[n8][2]*i1, Od[n8][3]*i1);
    }
}

// ---------------------------------------------------------------------------
extern "C" void kernel_launch(void* const* d_in, const int* in_sizes, int n_in,
                              void* d_out, int out_size)
{
    const float* x  = (const float*)d_in[0];
    const float* wq = (const float*)d_in[1];
    const float* wk = (const float*)d_in[2];
    const float* wv = (const float*)d_in[3];
    const float* wo = (const float*)d_in[4];
    float* out = (float*)d_out;

    float *q, *k, *v, *a;
    uint4* kpp; uint2* vpp;
    cudaGetSymbolAddress((void**)&q, g_q);
    cudaGetSymbolAddress((void**)&k, g_k);
    cudaGetSymbolAddress((void**)&v, g_v);
    cudaGetSymbolAddress((void**)&a, g_a);
    cudaGetSymbolAddress((void**)&kpp, g_kp);
    cudaGetSymbolAddress((void**)&vpp, g_vp);

    int smem_gemm = 65536;
    cudaFuncSetAttribute(gemm_tf32, cudaFuncAttributeMaxDynamicSharedMemorySize, smem_gemm);
    dim3 gg(Dq/128, Mrows/128);   // (8, 64)
    gemm_tf32<<<gg, 256, smem_gemm>>>(x, wq, q, Mrows, Dq, Dq);
    gemm_tf32<<<gg, 256, smem_gemm>>>(x, wk, k, Mrows, Dq, Dq);
    gemm_tf32<<<gg, 256, smem_gemm>>>(x, wv, v, Mrows, Dq, Dq);

    pack_kv<<<dim3(NTILES, 64), 256>>>(k, v, kpp, vpp);

    int smem_attn = 114688;   // 112KB -> 2 CTAs/SM
    cudaFuncSetAttribute(attn_tc, cudaFuncAttributeMaxDynamicSharedMemorySize, smem_attn);
    attn_tc<<<dim3(16, 64), 256, smem_attn>>>(q, kpp, vpp, a);

    gemm_tf32<<<gg, 256, smem_gemm>>>(a, wo, out, Mrows, Dq, Dq);
}

// round 6
// speedup vs baseline: 5.6511x; 1.2869x over previous
#include <cuda_runtime.h>
#include <cstdint>
#include <cstddef>

#define Bq 4
#define Sq 2048
#define Dq 1024
#define Hq 16
#define DKq 64
#define Mrows (Bq*Sq)
#define NTILES 32          // key tiles per (b,h)
#define NCH 32             // K chunks per GEMM (K=1024 / 32)
#define LNEG -1e30f

// Scratch (allocation-free rule: __device__ globals)
__device__ float g_q[Mrows*Dq];
__device__ float g_k[Mrows*Dq];
__device__ float g_v[Mrows*Dq];
__device__ float g_a[Mrows*Dq];
__device__ uint4 g_kp[(size_t)64*NTILES*2048];     // packed K fragments (hi+lo)
__device__ uint2 g_vp[(size_t)64*NTILES*2048];     // packed V fragments (hi only)
__device__ uint4 g_xp[(size_t)Mrows*Dq/4];          // packed x   (A layout)
__device__ uint4 g_ap[(size_t)Mrows*Dq/4];          // packed attn out (A layout)
__device__ uint4 g_wq[(size_t)Dq*Dq/4];             // packed weights (B layout)
__device__ uint4 g_wk[(size_t)Dq*Dq/4];
__device__ uint4 g_wv[(size_t)Dq*Dq/4];
__device__ uint4 g_wo[(size_t)Dq*Dq/4];

__device__ __forceinline__ uint32_t f2tf(float f) {
    uint32_t u;
    asm("cvt.rna.tf32.f32 %0, %1;" : "=r"(u) : "f"(f));
    return u;
}
__device__ __forceinline__ float ex2(float x) {
    float r;
    asm("ex2.approx.f32 %0, %1;" : "=f"(r) : "f"(x));
    return r;
}
__device__ __forceinline__ void mma_tf32(float* c, uint4 a, uint32_t b0, uint32_t b1) {
    asm volatile("mma.sync.aligned.m16n8k8.row.col.f32.tf32.tf32.f32 "
        "{%0,%1,%2,%3}, {%4,%5,%6,%7}, {%8,%9}, {%0,%1,%2,%3};"
        : "+f"(c[0]), "+f"(c[1]), "+f"(c[2]), "+f"(c[3])
        : "r"(a.x), "r"(a.y), "r"(a.z), "r"(a.w), "r"(b0), "r"(b1));
}
__device__ __forceinline__ void cp16(uint32_t sa, const void* g) {
    asm volatile("cp.async.cg.shared.global [%0], [%1], 16;" :: "r"(sa), "l"(g));
}

// ---------------------------------------------------------------------------
// Pack a float matrix [R x 1024] into A-layout fragment tiles (TF32).
// Tile (rb, ch) = 4096 u32, exactly the gemm smem A order. grid (R/128, 32).
// ---------------------------------------------------------------------------
__global__ void __launch_bounds__(256) pack_a(const float* __restrict__ A,
                                              uint32_t* __restrict__ out)
{
    const int rb = blockIdx.x, ch = blockIdx.y, tid = threadIdx.x;
    const int rbase = tid >> 3, kc = (tid & 7) << 2;
    const int ks = (tid & 7) >> 1, hi = tid & 1;
    uint32_t* ot = out + ((size_t)rb * NCH + ch) * 4096;
    const float* Ab = A + ((size_t)rb * 128) * Dq + ch * 32;
    #pragma unroll
    for (int i = 0; i < 4; ++i) {
        int r = rbase + 32*i;
        float4 f4 = *reinterpret_cast<const float4*>(Ab + (size_t)r * Dq + kc);
        const float* f = &f4.x;
        int mt = r >> 4, rr = r & 15;
        int w = (rr >> 3) + (hi << 1);
        int base = (mt*4 + ks) * 32;
        int l0 = (rr & 7) << 2;
        #pragma unroll
        for (int j = 0; j < 4; ++j)
            ot[(base + ((l0 + j) ^ (ks << 1))) * 4 + w] = f2tf(f[j]);
    }
}

// ---------------------------------------------------------------------------
// Pack the 4 weight matrices [1024 x 1024] into B-layout fragment tiles.
// grid (8, 32, 4); z selects the matrix.
// ---------------------------------------------------------------------------
__global__ void __launch_bounds__(256) pack_w(const float* __restrict__ w0,
                                              const float* __restrict__ w1,
                                              const float* __restrict__ w2,
                                              const float* __restrict__ w3,
                                              uint32_t* __restrict__ o0,
                                              uint32_t* __restrict__ o1,
                                              uint32_t* __restrict__ o2,
                                              uint32_t* __restrict__ o3)
{
    const float* W = (blockIdx.z == 0) ? w0 : (blockIdx.z == 1) ? w1
                    : (blockIdx.z == 2) ? w2 : w3;
    uint32_t* O = (blockIdx.z == 0) ? o0 : (blockIdx.z == 1) ? o1
                 : (blockIdx.z == 2) ? o2 : o3;
    const int nb = blockIdx.x, ch = blockIdx.y, tid = threadIdx.x;
    const int rbase = tid >> 3, kc = (tid & 7) << 2;
    const int ks = (tid & 7) >> 1, hi = tid & 1;
    uint32_t* ot = O + ((size_t)nb * NCH + ch) * 4096;
    const float* Wb = W + ((size_t)nb * 128) * Dq + ch * 32;
    #pragma unroll
    for (int i = 0; i < 4; ++i) {
        int n = rbase + 32*i;
        float4 f4 = *reinterpret_cast<const float4*>(Wb + (size_t)n * Dq + kc);
        const float* f = &f4.x;
        int nt = n >> 3, gg = n & 7;
        int w = ((nt & 1) << 1) + hi;
        int base = ((nt >> 1)*4 + ks) * 32;
        int l0 = gg << 2;
        #pragma unroll
        for (int j = 0; j < 4; ++j)
            ot[(base + ((l0 + j) ^ (ks << 1))) * 4 + w] = f2tf(f[j]);
    }
}

// ---------------------------------------------------------------------------
// TF32 GEMM on pre-packed operands: C[M,1024] = A @ W^T.
// BM=128, BN=128, 8 warps 4(m)x2(n), warp tile 32x64.
// 3-stage cp.async pipeline; mainloop = LDS fragments + mma only.
// Smem: 3 x (16KB A + 16KB B) = 96KB -> 2 CTAs/SM.
// ---------------------------------------------------------------------------
extern __shared__ uint32_t gsm[];
__global__ void __launch_bounds__(256, 2) gemm_packed(const uint4* __restrict__ Ap,
                                                      const uint4* __restrict__ Bp,
                                                      float* __restrict__ C, int M)
{
    const int tid = threadIdx.x;
    const int lane = tid & 31, wid = tid >> 5;
    const int wm = wid >> 1, wn = wid & 1;
    const int g = lane >> 2, t = lane & 3;
    const size_t tA0 = (size_t)blockIdx.y * NCH;   // tile indices
    const size_t tB0 = (size_t)blockIdx.x * NCH;
    const uint32_t sbase = (uint32_t)__cvta_generic_to_shared(gsm);

    float acc[2][8][4];
    #pragma unroll
    for (int mt = 0; mt < 2; ++mt)
        #pragma unroll
        for (int j = 0; j < 8; ++j)
            #pragma unroll
            for (int e = 0; e < 4; ++e) acc[mt][j][e] = 0.f;

    auto prefetch = [&](int ch, int s) {
        const uint4* ga = Ap + (tA0 + ch) * 1024 + tid;
        const uint4* gb = Bp + (tB0 + ch) * 1024 + tid;
        uint32_t sA = sbase + s * 32768;
        uint32_t sB = sA + 16384;
        #pragma unroll
        for (int i = 0; i < 4; ++i)
            cp16(sA + (tid + (i << 8)) * 16, ga + (i << 8));
        #pragma unroll
        for (int i = 0; i < 4; ++i)
            cp16(sB + (tid + (i << 8)) * 16, gb + (i << 8));
    };

    prefetch(0, 0);
    asm volatile("cp.async.commit_group;");
    prefetch(1, 1);
    asm volatile("cp.async.commit_group;");

    for (int ch = 0; ch < NCH; ++ch) {
        const int s = ch % 3;
        asm volatile("cp.async.wait_group 1;");
        __syncthreads();
        if (ch + 2 < NCH) prefetch(ch + 2, (ch + 2) % 3);
        asm volatile("cp.async.commit_group;");

        const uint32_t* As = gsm + s * 8192;
        const uint32_t* Bs = As + 4096;
        #pragma unroll
        for (int ks = 0; ks < 4; ++ks) {
            uint4 af[2], bf[4];
            const int sl = lane ^ (ks << 1);
            #pragma unroll
            for (int mt = 0; mt < 2; ++mt)
                af[mt] = *reinterpret_cast<const uint4*>(
                    &As[(((wm*2 + mt)*4 + ks)*32 + sl) * 4]);
            #pragma unroll
            for (int p = 0; p < 4; ++p)
                bf[p] = *reinterpret_cast<const uint4*>(
                    &Bs[(((wn*4 + p)*4 + ks)*32 + sl) * 4]);
            #pragma unroll
            for (int mt = 0; mt < 2; ++mt)
                #pragma unroll
                for (int p = 0; p < 4; ++p) {
                    mma_tf32(acc[mt][2*p],   af[mt], bf[p].x, bf[p].y);
                    mma_tf32(acc[mt][2*p+1], af[mt], bf[p].z, bf[p].w);
                }
        }
    }

    const int bm = blockIdx.y * 128, bn = blockIdx.x * 128;
    #pragma unroll
    for (int mt = 0; mt < 2; ++mt) {
        #pragma unroll
        for (int j = 0; j < 8; ++j) {
            int m = bm + wm*32 + mt*16 + g;
            int n = bn + wn*64 + j*8 + t*2;
            *reinterpret_cast<float2*>(C + (size_t)m * Dq + n)       = make_float2(acc[mt][j][0], acc[mt][j][1]);
            *reinterpret_cast<float2*>(C + (size_t)(m + 8) * Dq + n) = make_float2(acc[mt][j][2], acc[mt][j][3]);
        }
    }
}

// ---------------------------------------------------------------------------
// Pack K (hi+lo) and V (hi, transposed) into mma-fragment order (unchanged).
// ---------------------------------------------------------------------------
__global__ void __launch_bounds__(256) pack_kv(const float* __restrict__ Kg,
                                               const float* __restrict__ Vg,
                                               uint4* __restrict__ kp,
                                               uint2* __restrict__ vp)
{
    __shared__ float Vst[64*68];
    const int j = blockIdx.x, bh = blockIdx.y;
    const int b = bh >> 4, h = bh & 15;
    const size_t base = (size_t)b * Sq * Dq + (size_t)h * DKq;
    const int key0 = j << 6;
    const int tid = threadIdx.x;
    uint4* kpt = kp + ((size_t)bh * NTILES + j) * 2048;
    uint2* vpt = vp + ((size_t)bh * NTILES + j) * 2048;

    #pragma unroll
    for (int i = 0; i < 2; ++i) {
        int ta = tid + (i << 8);
        int kk = ta & 7, key = ta >> 3;
        const float* kq = Kg + base + (size_t)(key0 + key) * Dq + kk*8;
        float4 f0 = *reinterpret_cast<const float4*>(kq);
        float4 f1 = *reinterpret_cast<const float4*>(kq + 4);
        const float* p0 = &f0.x; const float* p1 = &f1.x;
        int sw = 4*(kk ^ (key & 7));
        int txor = (key >> 3) & 3;
        #pragma unroll
        for (int tt = 0; tt < 4; ++tt) {
            uint32_t h0 = f2tf(p0[tt]);
            uint32_t l0 = f2tf(p0[tt] - __uint_as_float(h0));
            uint32_t h1 = f2tf(p1[tt]);
            uint32_t l1 = f2tf(p1[tt] - __uint_as_float(h1));
            kpt[key*32 + sw + (tt ^ txor)] = make_uint4(h0, h1, l0, l1);
        }
    }
    #pragma unroll
    for (int i = 0; i < 4; ++i) {
        int id = tid + (i << 8);
        int rr = id >> 4, c4 = (id & 15) << 2;
        *reinterpret_cast<float4*>(Vst + rr*68 + c4) =
            *reinterpret_cast<const float4*>(Vg + base + (size_t)(key0 + rr) * Dq + c4);
    }
    __syncthreads();
    #pragma unroll
    for (int i = 0; i < 2; ++i) {
        int dk = tid & 63, kk = (tid >> 6) + (i << 2);
        float f[8];
        #pragma unroll
        for (int r = 0; r < 8; ++r) f[r] = Vst[(8*kk + r)*68 + dk];
        int sw = 4*(kk ^ (dk & 7));
        int txor = (dk >> 3) & 3;
        #pragma unroll
        for (int tt = 0; tt < 4; ++tt)
            vpt[dk*32 + sw + (tt ^ txor)] = make_uint2(f2tf(f[tt]), f2tf(f[tt+4]));
    }
}

// ---------------------------------------------------------------------------
// Tensor-core causal flash attention (R5 design, softmax in log2 domain).
// Q pre-scaled by 0.125*log2e; all exps are raw ex2.
// ---------------------------------------------------------------------------
extern __shared__ uint32_t sm_u[];
__global__ void __launch_bounds__(256, 2) attn_tc(const float* __restrict__ Qg,
                                                  const uint4* __restrict__ kp,
                                                  const uint2* __restrict__ vp,
                                                  float* __restrict__ Og)
{
    uint4* QA = reinterpret_cast<uint4*>(sm_u);            // 2048 u4
    uint4* KB = reinterpret_cast<uint4*>(sm_u + 8192);     // 2048 u4
    uint2* VB = reinterpret_cast<uint2*>(sm_u + 16384);    // 2048 u2
    uint4* PA = reinterpret_cast<uint4*>(sm_u + 20480);    // 2048 u4

    const int tid  = threadIdx.x;
    const int lane = tid & 31, w = tid >> 5;
    const int g = lane >> 2, t = lane & 3;
    const int qb = 15 - blockIdx.x;
    const int bh = blockIdx.y;
    const int b = bh >> 4, h = bh & 15;
    const size_t base = (size_t)b * Sq * Dq + (size_t)h * DKq;
    const int q0 = qb * 128;
    const float qsc = 0.125f * 1.44269504f;   // fold log2e into scale

    #pragma unroll
    for (int i = 0; i < 2; ++i) {
        int ta = tid + (i << 8);
        int kk = ta & 7, gg = (ta >> 3) & 7, sl = ta >> 6;
        int row = q0 + sl*16 + gg;
        const float* p0 = Qg + base + (size_t)row * Dq + kk*8;
        const float* p1 = p0 + 8*Dq;
        float4 a0 = *reinterpret_cast<const float4*>(p0);
        float4 a1 = *reinterpret_cast<const float4*>(p0 + 4);
        float4 b0 = *reinterpret_cast<const float4*>(p1);
        float4 b1 = *reinterpret_cast<const float4*>(p1 + 4);
        const float* fa0 = &a0.x; const float* fa1 = &a1.x;
        const float* fb0 = &b0.x; const float* fb1 = &b1.x;
        #pragma unroll
        for (int tt = 0; tt < 4; ++tt) {
            QA[sl*256 + gg*32 + 4*(kk ^ gg) + tt] =
                make_uint4(f2tf(fa0[tt]*qsc), f2tf(fb0[tt]*qsc),
                           f2tf(fa1[tt]*qsc), f2tf(fb1[tt]*qsc));
        }
    }

    const int row_hi = q0 + w*16 + 15;
    float mst0 = LNEG, mst1 = LNEG, lst0 = 0.f, lst1 = 0.f;
    float Od[8][4];
    #pragma unroll
    for (int n8 = 0; n8 < 8; ++n8)
        #pragma unroll
        for (int e = 0; e < 4; ++e) Od[n8][e] = 0.f;

    const int jmax = 2*qb + 1;
    for (int j = 0; j <= jmax; ++j) {
        const int key0 = j << 6;
        __syncthreads();

        const uint4* kpt = kp + ((size_t)bh * NTILES + j) * 2048;
        const uint2* vpt = vp + ((size_t)bh * NTILES + j) * 2048;
        #pragma unroll
        for (int i = 0; i < 8; ++i)
            KB[tid + (i << 8)] = kpt[tid + (i << 8)];
        #pragma unroll
        for (int i = 0; i < 8; ++i)
            VB[tid + (i << 8)] = vpt[tid + (i << 8)];
        __syncthreads();

        if (key0 <= row_hi) {
            float acc[8][4];
            #pragma unroll
            for (int n8 = 0; n8 < 8; ++n8)
                #pragma unroll
                for (int e = 0; e < 4; ++e) acc[n8][e] = 0.f;

            #pragma unroll
            for (int kk = 0; kk < 8; ++kk) {
                uint4 aq = QA[w*256 + g*32 + 4*(kk ^ g) + t];
                #pragma unroll
                for (int n8 = 0; n8 < 8; ++n8) {
                    uint4 kb = KB[(8*n8 + g)*32 + 4*(kk ^ g) + (t ^ (n8 & 3))];
                    mma_tf32(acc[n8], aq, kb.x, kb.y);
                    mma_tf32(acc[n8], aq, kb.z, kb.w);
                }
            }
            if (j >= 2*qb) {
                int r0 = q0 + w*16 + g, r1 = r0 + 8;
                #pragma unroll
                for (int n8 = 0; n8 < 8; ++n8) {
                    int c0 = key0 + 8*n8 + 2*t, c1 = c0 + 1;
                    if (c0 > r0) acc[n8][0] = LNEG;
                    if (c1 > r0) acc[n8][1] = LNEG;
                    if (c0 > r1) acc[n8][2] = LNEG;
                    if (c1 > r1) acc[n8][3] = LNEG;
                }
            }
            float t0 = LNEG, t1 = LNEG;
            #pragma unroll
            for (int n8 = 0; n8 < 8; ++n8) {
                t0 = fmaxf(t0, fmaxf(acc[n8][0], acc[n8][1]));
                t1 = fmaxf(t1, fmaxf(acc[n8][2], acc[n8][3]));
            }
            t0 = fmaxf(t0, __shfl_xor_sync(0xffffffffu, t0, 1));
            t0 = fmaxf(t0, __shfl_xor_sync(0xffffffffu, t0, 2));
            t1 = fmaxf(t1, __shfl_xor_sync(0xffffffffu, t1, 1));
            t1 = fmaxf(t1, __shfl_xor_sync(0xffffffffu, t1, 2));
            float m0n = fmaxf(mst0, t0), m1n = fmaxf(mst1, t1);
            float c0 = ex2(mst0 - m0n), c1 = ex2(mst1 - m1n);
            float s0 = 0.f, s1 = 0.f;

            int d0 = 2*t, d1 = 2*t + 1;
            int tw0 = d0 & 3, sl0 = (d0 >> 2) << 1;
            int tw1 = d1 & 3, sl1 = (d1 >> 2) << 1;
            #pragma unroll
            for (int n8 = 0; n8 < 8; ++n8) {
                float p00 = ex2(acc[n8][0] - m0n);
                float p01 = ex2(acc[n8][1] - m0n);
                float p10 = ex2(acc[n8][2] - m1n);
                float p11 = ex2(acc[n8][3] - m1n);
                s0 += p00 + p01;
                s1 += p10 + p11;
                uint32_t* pw = reinterpret_cast<uint32_t*>(&PA[w*256 + g*32 + 4*(n8 ^ g)]);
                pw[tw0*4 + sl0]     = f2tf(p00);
                pw[tw0*4 + sl0 + 1] = f2tf(p10);
                pw[tw1*4 + sl1]     = f2tf(p01);
                pw[tw1*4 + sl1 + 1] = f2tf(p11);
            }
            lst0 = lst0 * c0 + s0;
            lst1 = lst1 * c1 + s1;
            mst0 = m0n; mst1 = m1n;
            #pragma unroll
            for (int n8 = 0; n8 < 8; ++n8) {
                Od[n8][0] *= c0; Od[n8][1] *= c0;
                Od[n8][2] *= c1; Od[n8][3] *= c1;
            }
            __syncwarp();

            #pragma unroll
            for (int kk = 0; kk < 8; ++kk) {
                uint4 pa = PA[w*256 + g*32 + 4*(kk ^ g) + t];
                #pragma unroll
                for (int n8 = 0; n8 < 8; ++n8) {
                    uint2 vb = VB[(8*n8 + g)*32 + 4*(kk ^ g) + (t ^ (n8 & 3))];
                    mma_tf32(Od[n8], pa, vb.x, vb.y);
                }
            }
        }
    }

    lst0 += __shfl_xor_sync(0xffffffffu, lst0, 1);
    lst0 += __shfl_xor_sync(0xffffffffu, lst0, 2);
    lst1 += __shfl_xor_sync(0xffffffffu, lst1, 1);
    lst1 += __shfl_xor_sync(0xffffffffu, lst1, 2);
    float i0 = 1.f / lst0, i1 = 1.f / lst1;
    int r0 = q0 + w*16 + g;
    #pragma unroll
    for (int n8 = 0; n8 < 8; ++n8) {
        int col = h*64 + 8*n8 + 2*t;
        size_t o0 = (size_t)((size_t)b * Sq + r0) * Dq + col;
        *reinterpret_cast<float2*>(Og + o0)          = make_float2(Od[n8][0]*i0, Od[n8][1]*i0);
        *reinterpret_cast<float2*>(Og + o0 + 8*Dq)   = make_float2(Od[n8][2]*i1, Od[n8][3]*i1);
    }
}

// ---------------------------------------------------------------------------
extern "C" void kernel_launch(void* const* d_in, const int* in_sizes, int n_in,
                              void* d_out, int out_size)
{
    const float* x  = (const float*)d_in[0];
    const float* wq = (const float*)d_in[1];
    const float* wk = (const float*)d_in[2];
    const float* wv = (const float*)d_in[3];
    const float* wo = (const float*)d_in[4];
    float* out = (float*)d_out;

    float *q, *k, *v, *a;
    uint4 *kpp, *xp, *ap, *pwq, *pwk, *pwv, *pwo;
    uint2 *vpp;
    cudaGetSymbolAddress((void**)&q,   g_q);
    cudaGetSymbolAddress((void**)&k,   g_k);
    cudaGetSymbolAddress((void**)&v,   g_v);
    cudaGetSymbolAddress((void**)&a,   g_a);
    cudaGetSymbolAddress((void**)&kpp, g_kp);
    cudaGetSymbolAddress((void**)&vpp, g_vp);
    cudaGetSymbolAddress((void**)&xp,  g_xp);
    cudaGetSymbolAddress((void**)&ap,  g_ap);
    cudaGetSymbolAddress((void**)&pwq, g_wq);
    cudaGetSymbolAddress((void**)&pwk, g_wk);
    cudaGetSymbolAddress((void**)&pwv, g_wv);
    cudaGetSymbolAddress((void**)&pwo, g_wo);

    // Pack inputs into fragment order (off the hot path)
    pack_a<<<dim3(Mrows/128, NCH), 256>>>(x, (uint32_t*)xp);
    pack_w<<<dim3(8, NCH, 4), 256>>>(wq, wk, wv, wo,
                                     (uint32_t*)pwq, (uint32_t*)pwk,
                                     (uint32_t*)pwv, (uint32_t*)pwo);

    int smem_gemm = 98304;   // 96KB, 3 stages
    cudaFuncSetAttribute(gemm_packed, cudaFuncAttributeMaxDynamicSharedMemorySize, smem_gemm);
    dim3 gg(Dq/128, Mrows/128);   // (8, 64)
    gemm_packed<<<gg, 256, smem_gemm>>>(xp, pwq, q, Mrows);
    gemm_packed<<<gg, 256, smem_gemm>>>(xp, pwk, k, Mrows);
    gemm_packed<<<gg, 256, smem_gemm>>>(xp, pwv, v, Mrows);

    pack_kv<<<dim3(NTILES, 64), 256>>>(k, v, kpp, vpp);

    int smem_attn = 114688;   // 112KB -> 2 CTAs/SM
    cudaFuncSetAttribute(attn_tc, cudaFuncAttributeMaxDynamicSharedMemorySize, smem_attn);
    attn_tc<<<dim3(16, 64), 256, smem_attn>>>(q, kpp, vpp, a);

    pack_a<<<dim3(Mrows/128, NCH), 256>>>(a, (uint32_t*)ap);
    gemm_packed<<<gg, 256, smem_gemm>>>(ap, pwo, out, Mrows);
}

// round 7
// speedup vs baseline: 5.8801x; 1.0405x over previous
#include <cuda_runtime.h>
#include <cstdint>
#include <cstddef>

#define Bq 4
#define Sq 2048
#define Dq 1024
#define Hq 16
#define DKq 64
#define Mrows (Bq*Sq)
#define NTILES 32          // key tiles per (b,h)
#define NCH 32             // K chunks per GEMM (K=1024 / 32)
#define LNEG -1e30f

// Scratch (allocation-free rule: __device__ globals)
__device__ float g_q[Mrows*Dq];
__device__ float g_k[Mrows*Dq];
__device__ float g_v[Mrows*Dq];
__device__ float g_a[Mrows*Dq];
__device__ uint4 g_kp[(size_t)64*NTILES*2048];     // packed K fragments (hi+lo)
__device__ uint2 g_vp[(size_t)64*NTILES*2048];     // packed V fragments (hi only)
__device__ uint4 g_xp[(size_t)Mrows*Dq/4];          // packed x   (A layout)
__device__ uint4 g_ap[(size_t)Mrows*Dq/4];          // packed attn out (A layout)
__device__ uint4 g_wq[(size_t)Dq*Dq/4];             // packed weights (B layout)
__device__ uint4 g_wk[(size_t)Dq*Dq/4];
__device__ uint4 g_wv[(size_t)Dq*Dq/4];
__device__ uint4 g_wo[(size_t)Dq*Dq/4];

__device__ __forceinline__ uint32_t f2tf(float f) {
    uint32_t u;
    asm("cvt.rna.tf32.f32 %0, %1;" : "=r"(u) : "f"(f));
    return u;
}
__device__ __forceinline__ float ex2(float x) {
    float r;
    asm("ex2.approx.f32 %0, %1;" : "=f"(r) : "f"(x));
    return r;
}
__device__ __forceinline__ void mma_tf32(float* c, uint4 a, uint32_t b0, uint32_t b1) {
    asm volatile("mma.sync.aligned.m16n8k8.row.col.f32.tf32.tf32.f32 "
        "{%0,%1,%2,%3}, {%4,%5,%6,%7}, {%8,%9}, {%0,%1,%2,%3};"
        : "+f"(c[0]), "+f"(c[1]), "+f"(c[2]), "+f"(c[3])
        : "r"(a.x), "r"(a.y), "r"(a.z), "r"(a.w), "r"(b0), "r"(b1));
}
__device__ __forceinline__ void cp16(uint32_t sa, const void* g) {
    asm volatile("cp.async.cg.shared.global [%0], [%1], 16;" :: "r"(sa), "l"(g));
}

// ---------------------------------------------------------------------------
// Pack a float matrix [R x 1024] into A-layout fragment tiles (TF32).
// ---------------------------------------------------------------------------
__global__ void __launch_bounds__(256) pack_a(const float* __restrict__ A,
                                              uint32_t* __restrict__ out)
{
    const int rb = blockIdx.x, ch = blockIdx.y, tid = threadIdx.x;
    const int rbase = tid >> 3, kc = (tid & 7) << 2;
    const int ks = (tid & 7) >> 1, hi = tid & 1;
    uint32_t* ot = out + ((size_t)rb * NCH + ch) * 4096;
    const float* Ab = A + ((size_t)rb * 128) * Dq + ch * 32;
    #pragma unroll
    for (int i = 0; i < 4; ++i) {
        int r = rbase + 32*i;
        float4 f4 = *reinterpret_cast<const float4*>(Ab + (size_t)r * Dq + kc);
        const float* f = &f4.x;
        int mt = r >> 4, rr = r & 15;
        int w = (rr >> 3) + (hi << 1);
        int base = (mt*4 + ks) * 32;
        int l0 = (rr & 7) << 2;
        #pragma unroll
        for (int j = 0; j < 4; ++j)
            ot[(base + ((l0 + j) ^ (ks << 1))) * 4 + w] = f2tf(f[j]);
    }
}

// ---------------------------------------------------------------------------
// Pack the 4 weight matrices into B-layout fragment tiles.
// ---------------------------------------------------------------------------
__global__ void __launch_bounds__(256) pack_w(const float* __restrict__ w0,
                                              const float* __restrict__ w1,
                                              const float* __restrict__ w2,
                                              const float* __restrict__ w3,
                                              uint32_t* __restrict__ o0,
                                              uint32_t* __restrict__ o1,
                                              uint32_t* __restrict__ o2,
                                              uint32_t* __restrict__ o3)
{
    const float* W = (blockIdx.z == 0) ? w0 : (blockIdx.z == 1) ? w1
                    : (blockIdx.z == 2) ? w2 : w3;
    uint32_t* O = (blockIdx.z == 0) ? o0 : (blockIdx.z == 1) ? o1
                 : (blockIdx.z == 2) ? o2 : o3;
    const int nb = blockIdx.x, ch = blockIdx.y, tid = threadIdx.x;
    const int rbase = tid >> 3, kc = (tid & 7) << 2;
    const int ks = (tid & 7) >> 1, hi = tid & 1;
    uint32_t* ot = O + ((size_t)nb * NCH + ch) * 4096;
    const float* Wb = W + ((size_t)nb * 128) * Dq + ch * 32;
    #pragma unroll
    for (int i = 0; i < 4; ++i) {
        int n = rbase + 32*i;
        float4 f4 = *reinterpret_cast<const float4*>(Wb + (size_t)n * Dq + kc);
        const float* f = &f4.x;
        int nt = n >> 3, gg = n & 7;
        int w = ((nt & 1) << 1) + hi;
        int base = ((nt >> 1)*4 + ks) * 32;
        int l0 = gg << 2;
        #pragma unroll
        for (int j = 0; j < 4; ++j)
            ot[(base + ((l0 + j) ^ (ks << 1))) * 4 + w] = f2tf(f[j]);
    }
}

// ---------------------------------------------------------------------------
// TF32 GEMM on pre-packed operands (unchanged from R6).
// ---------------------------------------------------------------------------
extern __shared__ uint32_t gsm[];
__global__ void __launch_bounds__(256, 2) gemm_packed(const uint4* __restrict__ Ap,
                                                      const uint4* __restrict__ Bp,
                                                      float* __restrict__ C, int M)
{
    const int tid = threadIdx.x;
    const int lane = tid & 31, wid = tid >> 5;
    const int wm = wid >> 1, wn = wid & 1;
    const int g = lane >> 2, t = lane & 3;
    const size_t tA0 = (size_t)blockIdx.y * NCH;
    const size_t tB0 = (size_t)blockIdx.x * NCH;
    const uint32_t sbase = (uint32_t)__cvta_generic_to_shared(gsm);

    float acc[2][8][4];
    #pragma unroll
    for (int mt = 0; mt < 2; ++mt)
        #pragma unroll
        for (int j = 0; j < 8; ++j)
            #pragma unroll
            for (int e = 0; e < 4; ++e) acc[mt][j][e] = 0.f;

    auto prefetch = [&](int ch, int s) {
        const uint4* ga = Ap + (tA0 + ch) * 1024 + tid;
        const uint4* gb = Bp + (tB0 + ch) * 1024 + tid;
        uint32_t sA = sbase + s * 32768;
        uint32_t sB = sA + 16384;
        #pragma unroll
        for (int i = 0; i < 4; ++i)
            cp16(sA + (tid + (i << 8)) * 16, ga + (i << 8));
        #pragma unroll
        for (int i = 0; i < 4; ++i)
            cp16(sB + (tid + (i << 8)) * 16, gb + (i << 8));
    };

    prefetch(0, 0);
    asm volatile("cp.async.commit_group;");
    prefetch(1, 1);
    asm volatile("cp.async.commit_group;");

    for (int ch = 0; ch < NCH; ++ch) {
        const int s = ch % 3;
        asm volatile("cp.async.wait_group 1;");
        __syncthreads();
        if (ch + 2 < NCH) prefetch(ch + 2, (ch + 2) % 3);
        asm volatile("cp.async.commit_group;");

        const uint32_t* As = gsm + s * 8192;
        const uint32_t* Bs = As + 4096;
        #pragma unroll
        for (int ks = 0; ks < 4; ++ks) {
            uint4 af[2], bf[4];
            const int sl = lane ^ (ks << 1);
            #pragma unroll
            for (int mt = 0; mt < 2; ++mt)
                af[mt] = *reinterpret_cast<const uint4*>(
                    &As[(((wm*2 + mt)*4 + ks)*32 + sl) * 4]);
            #pragma unroll
            for (int p = 0; p < 4; ++p)
                bf[p] = *reinterpret_cast<const uint4*>(
                    &Bs[(((wn*4 + p)*4 + ks)*32 + sl) * 4]);
            #pragma unroll
            for (int mt = 0; mt < 2; ++mt)
                #pragma unroll
                for (int p = 0; p < 4; ++p) {
                    mma_tf32(acc[mt][2*p],   af[mt], bf[p].x, bf[p].y);
                    mma_tf32(acc[mt][2*p+1], af[mt], bf[p].z, bf[p].w);
                }
        }
    }

    const int bm = blockIdx.y * 128, bn = blockIdx.x * 128;
    #pragma unroll
    for (int mt = 0; mt < 2; ++mt) {
        #pragma unroll
        for (int j = 0; j < 8; ++j) {
            int m = bm + wm*32 + mt*16 + g;
            int n = bn + wn*64 + j*8 + t*2;
            *reinterpret_cast<float2*>(C + (size_t)m * Dq + n)       = make_float2(acc[mt][j][0], acc[mt][j][1]);
            *reinterpret_cast<float2*>(C + (size_t)(m + 8) * Dq + n) = make_float2(acc[mt][j][2], acc[mt][j][3]);
        }
    }
}

// ---------------------------------------------------------------------------
// Pack K (hi+lo) and V (hi, transposed) into mma-fragment order (unchanged).
// ---------------------------------------------------------------------------
__global__ void __launch_bounds__(256) pack_kv(const float* __restrict__ Kg,
                                               const float* __restrict__ Vg,
                                               uint4* __restrict__ kp,
                                               uint2* __restrict__ vp)
{
    __shared__ float Vst[64*68];
    const int j = blockIdx.x, bh = blockIdx.y;
    const int b = bh >> 4, h = bh & 15;
    const size_t base = (size_t)b * Sq * Dq + (size_t)h * DKq;
    const int key0 = j << 6;
    const int tid = threadIdx.x;
    uint4* kpt = kp + ((size_t)bh * NTILES + j) * 2048;
    uint2* vpt = vp + ((size_t)bh * NTILES + j) * 2048;

    #pragma unroll
    for (int i = 0; i < 2; ++i) {
        int ta = tid + (i << 8);
        int kk = ta & 7, key = ta >> 3;
        const float* kq = Kg + base + (size_t)(key0 + key) * Dq + kk*8;
        float4 f0 = *reinterpret_cast<const float4*>(kq);
        float4 f1 = *reinterpret_cast<const float4*>(kq + 4);
        const float* p0 = &f0.x; const float* p1 = &f1.x;
        int sw = 4*(kk ^ (key & 7));
        int txor = (key >> 3) & 3;
        #pragma unroll
        for (int tt = 0; tt < 4; ++tt) {
            uint32_t h0 = f2tf(p0[tt]);
            uint32_t l0 = f2tf(p0[tt] - __uint_as_float(h0));
            uint32_t h1 = f2tf(p1[tt]);
            uint32_t l1 = f2tf(p1[tt] - __uint_as_float(h1));
            kpt[key*32 + sw + (tt ^ txor)] = make_uint4(h0, h1, l0, l1);
        }
    }
    #pragma unroll
    for (int i = 0; i < 4; ++i) {
        int id = tid + (i << 8);
        int rr = id >> 4, c4 = (id & 15) << 2;
        *reinterpret_cast<float4*>(Vst + rr*68 + c4) =
            *reinterpret_cast<const float4*>(Vg + base + (size_t)(key0 + rr) * Dq + c4);
    }
    __syncthreads();
    #pragma unroll
    for (int i = 0; i < 2; ++i) {
        int dk = tid & 63, kk = (tid >> 6) + (i << 2);
        float f[8];
        #pragma unroll
        for (int r = 0; r < 8; ++r) f[r] = Vst[(8*kk + r)*68 + dk];
        int sw = 4*(kk ^ (dk & 7));
        int txor = (dk >> 3) & 3;
        #pragma unroll
        for (int tt = 0; tt < 4; ++tt)
            vpt[dk*32 + sw + (tt ^ txor)] = make_uint2(f2tf(f[tt]), f2tf(f[tt+4]));
    }
}

// ---------------------------------------------------------------------------
// Tensor-core causal flash attention.
// Block = 256 q-rows of one (b,h); 512 threads = 16 warps x m16; n=64 tiles.
// KB/VB double-buffered via cp.async (copy of tile j+1 overlaps compute of j).
// Smem (u32 offsets): QA 0..16K | PA 16K..32K | KB 32K+s*8K | VB 48K+... 224KB.
// ---------------------------------------------------------------------------
extern __shared__ uint32_t sm_u[];
__global__ void __launch_bounds__(512, 1) attn_tc(const float* __restrict__ Qg,
                                                  const uint4* __restrict__ kp,
                                                  const uint2* __restrict__ vp,
                                                  float* __restrict__ Og)
{
    uint4* QA = reinterpret_cast<uint4*>(sm_u);              // 4096 u4 (64KB)
    uint4* PA = reinterpret_cast<uint4*>(sm_u + 16384);      // 4096 u4 (64KB)
    const uint32_t sbase = (uint32_t)__cvta_generic_to_shared(sm_u);

    const int tid  = threadIdx.x;
    const int lane = tid & 31, w = tid >> 5;                 // w: 0..15
    const int g = lane >> 2, t = lane & 3;
    const int qb = 7 - blockIdx.x;                           // heavy blocks first
    const int bh = blockIdx.y;
    const int b = bh >> 4, h = bh & 15;
    const size_t base = (size_t)b * Sq * Dq + (size_t)h * DKq;
    const int q0 = qb * 256;
    const float qsc = 0.125f * 1.44269504f;                  // fold log2e

    // ---- Build QA once (256 rows) ----
    #pragma unroll
    for (int i = 0; i < 2; ++i) {
        int ta = tid + (i << 9);
        int kk = ta & 7, gg = (ta >> 3) & 7, sl = ta >> 6;   // sl: 0..15
        int row = q0 + sl*16 + gg;
        const float* p0 = Qg + base + (size_t)row * Dq + kk*8;
        const float* p1 = p0 + 8*Dq;
        float4 a0 = *reinterpret_cast<const float4*>(p0);
        float4 a1 = *reinterpret_cast<const float4*>(p0 + 4);
        float4 b0 = *reinterpret_cast<const float4*>(p1);
        float4 b1 = *reinterpret_cast<const float4*>(p1 + 4);
        const float* fa0 = &a0.x; const float* fa1 = &a1.x;
        const float* fb0 = &b0.x; const float* fb1 = &b1.x;
        #pragma unroll
        for (int tt = 0; tt < 4; ++tt) {
            QA[sl*256 + gg*32 + 4*(kk ^ gg) + tt] =
                make_uint4(f2tf(fa0[tt]*qsc), f2tf(fb0[tt]*qsc),
                           f2tf(fa1[tt]*qsc), f2tf(fb1[tt]*qsc));
        }
    }

    auto prefetch = [&](int j, int s) {
        const uint4* kpt  = kp + ((size_t)bh * NTILES + j) * 2048;
        const uint4* vpt4 = reinterpret_cast<const uint4*>(vp) + ((size_t)bh * NTILES + j) * 1024;
        uint32_t sK = sbase + (32768 + s * 8192) * 4;
        uint32_t sV = sbase + (49152 + s * 4096) * 4;
        #pragma unroll
        for (int i = 0; i < 4; ++i)
            cp16(sK + (tid + (i << 9)) * 16, kpt + tid + (i << 9));
        #pragma unroll
        for (int i = 0; i < 2; ++i)
            cp16(sV + (tid + (i << 9)) * 16, vpt4 + tid + (i << 9));
    };

    const int row_hi = q0 + w*16 + 15;
    float mst0 = LNEG, mst1 = LNEG, lst0 = 0.f, lst1 = 0.f;
    float Od[8][4];
    #pragma unroll
    for (int n8 = 0; n8 < 8; ++n8)
        #pragma unroll
        for (int e = 0; e < 4; ++e) Od[n8][e] = 0.f;

    const int jmax = 4*qb + 3;
    prefetch(0, 0);
    asm volatile("cp.async.commit_group;");

    for (int j = 0; j <= jmax; ++j) {
        const int s = j & 1;
        const int key0 = j << 6;
        if (j + 1 <= jmax) prefetch(j + 1, s ^ 1);   // stage s^1 free (synced last iter)
        asm volatile("cp.async.commit_group;");
        asm volatile("cp.async.wait_group 1;");      // tile j arrived (this thread)
        __syncthreads();                              // ... and all other threads'

        if (key0 <= row_hi) {
            const uint4* KBs = reinterpret_cast<const uint4*>(sm_u + 32768 + s * 8192);
            const uint2* VBs = reinterpret_cast<const uint2*>(sm_u + 49152 + s * 4096);

            // ---- QK^T (K hi+lo) ----
            float acc[8][4];
            #pragma unroll
            for (int n8 = 0; n8 < 8; ++n8)
                #pragma unroll
                for (int e = 0; e < 4; ++e) acc[n8][e] = 0.f;

            #pragma unroll
            for (int kk = 0; kk < 8; ++kk) {
                uint4 aq = QA[w*256 + g*32 + 4*(kk ^ g) + t];
                #pragma unroll
                for (int n8 = 0; n8 < 8; ++n8) {
                    uint4 kb = KBs[(8*n8 + g)*32 + 4*(kk ^ g) + (t ^ (n8 & 3))];
                    mma_tf32(acc[n8], aq, kb.x, kb.y);
                    mma_tf32(acc[n8], aq, kb.z, kb.w);
                }
            }
            // ---- causal mask (tiles that can clip this warp) ----
            if (key0 + 63 > q0 + w*16) {
                int r0 = q0 + w*16 + g, r1 = r0 + 8;
                #pragma unroll
                for (int n8 = 0; n8 < 8; ++n8) {
                    int c0 = key0 + 8*n8 + 2*t, c1 = c0 + 1;
                    if (c0 > r0) acc[n8][0] = LNEG;
                    if (c1 > r0) acc[n8][1] = LNEG;
                    if (c0 > r1) acc[n8][2] = LNEG;
                    if (c1 > r1) acc[n8][3] = LNEG;
                }
            }
            // ---- online softmax (log2 domain) ----
            float t0 = LNEG, t1 = LNEG;
            #pragma unroll
            for (int n8 = 0; n8 < 8; ++n8) {
                t0 = fmaxf(t0, fmaxf(acc[n8][0], acc[n8][1]));
                t1 = fmaxf(t1, fmaxf(acc[n8][2], acc[n8][3]));
            }
            t0 = fmaxf(t0, __shfl_xor_sync(0xffffffffu, t0, 1));
            t0 = fmaxf(t0, __shfl_xor_sync(0xffffffffu, t0, 2));
            t1 = fmaxf(t1, __shfl_xor_sync(0xffffffffu, t1, 1));
            t1 = fmaxf(t1, __shfl_xor_sync(0xffffffffu, t1, 2));
            float m0n = fmaxf(mst0, t0), m1n = fmaxf(mst1, t1);
            float c0 = ex2(mst0 - m0n), c1 = ex2(mst1 - m1n);
            float s0 = 0.f, s1 = 0.f;

            int d0 = 2*t, d1 = 2*t + 1;
            int tw0 = d0 & 3, sl0 = (d0 >> 2) << 1;
            int tw1 = d1 & 3, sl1 = (d1 >> 2) << 1;
            #pragma unroll
            for (int n8 = 0; n8 < 8; ++n8) {
                float p00 = ex2(acc[n8][0] - m0n);
                float p01 = ex2(acc[n8][1] - m0n);
                float p10 = ex2(acc[n8][2] - m1n);
                float p11 = ex2(acc[n8][3] - m1n);
                s0 += p00 + p01;
                s1 += p10 + p11;
                uint32_t* pw = reinterpret_cast<uint32_t*>(&PA[w*256 + g*32 + 4*(n8 ^ g)]);
                pw[tw0*4 + sl0]     = f2tf(p00);
                pw[tw0*4 + sl0 + 1] = f2tf(p10);
                pw[tw1*4 + sl1]     = f2tf(p01);
                pw[tw1*4 + sl1 + 1] = f2tf(p11);
            }
            lst0 = lst0 * c0 + s0;       // per-lane partials; c row-uniform
            lst1 = lst1 * c1 + s1;
            mst0 = m0n; mst1 = m1n;
            #pragma unroll
            for (int n8 = 0; n8 < 8; ++n8) {
                Od[n8][0] *= c0; Od[n8][1] *= c0;
                Od[n8][2] *= c1; Od[n8][3] *= c1;
            }
            __syncwarp();

            // ---- P @ V (V hi only) ----
            #pragma unroll
            for (int kk = 0; kk < 8; ++kk) {
                uint4 pa = PA[w*256 + g*32 + 4*(kk ^ g) + t];
                #pragma unroll
                for (int n8 = 0; n8 < 8; ++n8) {
                    uint2 vb = VBs[(8*n8 + g)*32 + 4*(kk ^ g) + (t ^ (n8 & 3))];
                    mma_tf32(Od[n8], pa, vb.x, vb.y);
                }
            }
        }
        __syncthreads();                 // stage s free for prefetch at j+1
    }

    // ---- epilogue: reduce per-lane l partials across the 4 t-lanes ----
    lst0 += __shfl_xor_sync(0xffffffffu, lst0, 1);
    lst0 += __shfl_xor_sync(0xffffffffu, lst0, 2);
    lst1 += __shfl_xor_sync(0xffffffffu, lst1, 1);
    lst1 += __shfl_xor_sync(0xffffffffu, lst1, 2);
    float i0 = 1.f / lst0, i1 = 1.f / lst1;
    int r0 = q0 + w*16 + g;
    #pragma unroll
    for (int n8 = 0; n8 < 8; ++n8) {
        int col = h*64 + 8*n8 + 2*t;
        size_t o0 = (size_t)((size_t)b * Sq + r0) * Dq + col;
        *reinterpret_cast<float2*>(Og + o0)          = make_float2(Od[n8][0]*i0, Od[n8][1]*i0);
        *reinterpret_cast<float2*>(Og + o0 + 8*Dq)   = make_float2(Od[n8][2]*i1, Od[n8][3]*i1);
    }
}

// ---------------------------------------------------------------------------
extern "C" void kernel_launch(void* const* d_in, const int* in_sizes, int n_in,
                              void* d_out, int out_size)
{
    const float* x  = (const float*)d_in[0];
    const float* wq = (const float*)d_in[1];
    const float* wk = (const float*)d_in[2];
    const float* wv = (const float*)d_in[3];
    const float* wo = (const float*)d_in[4];
    float* out = (float*)d_out;

    float *q, *k, *v, *a;
    uint4 *kpp, *xp, *ap, *pwq, *pwk, *pwv, *pwo;
    uint2 *vpp;
    cudaGetSymbolAddress((void**)&q,   g_q);
    cudaGetSymbolAddress((void**)&k,   g_k);
    cudaGetSymbolAddress((void**)&v,   g_v);
    cudaGetSymbolAddress((void**)&a,   g_a);
    cudaGetSymbolAddress((void**)&kpp, g_kp);
    cudaGetSymbolAddress((void**)&vpp, g_vp);
    cudaGetSymbolAddress((void**)&xp,  g_xp);
    cudaGetSymbolAddress((void**)&ap,  g_ap);
    cudaGetSymbolAddress((void**)&pwq, g_wq);
    cudaGetSymbolAddress((void**)&pwk, g_wk);
    cudaGetSymbolAddress((void**)&pwv, g_wv);
    cudaGetSymbolAddress((void**)&pwo, g_wo);

    pack_a<<<dim3(Mrows/128, NCH), 256>>>(x, (uint32_t*)xp);
    pack_w<<<dim3(8, NCH, 4), 256>>>(wq, wk, wv, wo,
                                     (uint32_t*)pwq, (uint32_t*)pwk,
                                     (uint32_t*)pwv, (uint32_t*)pwo);

    int smem_gemm = 98304;
    cudaFuncSetAttribute(gemm_packed, cudaFuncAttributeMaxDynamicSharedMemorySize, smem_gemm);
    dim3 gg(Dq/128, Mrows/128);
    gemm_packed<<<gg, 256, smem_gemm>>>(xp, pwq, q, Mrows);
    gemm_packed<<<gg, 256, smem_gemm>>>(xp, pwk, k, Mrows);
    gemm_packed<<<gg, 256, smem_gemm>>>(xp, pwv, v, Mrows);

    pack_kv<<<dim3(NTILES, 64), 256>>>(k, v, kpp, vpp);

    int smem_attn = 229376;   // 224KB: QA 64 | PA 64 | KB 2x32 | VB 2x16
    cudaFuncSetAttribute(attn_tc, cudaFuncAttributeMaxDynamicSharedMemorySize, smem_attn);
    attn_tc<<<dim3(8, 64), 512, smem_attn>>>(q, kpp, vpp, a);

    pack_a<<<dim3(Mrows/128, NCH), 256>>>(a, (uint32_t*)ap);
    gemm_packed<<<gg, 256, smem_gemm>>>(ap, pwo, out, Mrows);
}

// round 8
// speedup vs baseline: 6.6928x; 1.1382x over previous
#include <cuda_runtime.h>
#include <cstdint>
#include <cstddef>

#define Bq 4
#define Sq 2048
#define Dq 1024
#define Hq 16
#define DKq 64
#define Mrows (Bq*Sq)
#define NTILES 32          // key tiles per (b,h)
#define NCH 32             // K chunks per GEMM (K=1024 / 32)
#define LNEG -1e30f

// Scratch (allocation-free rule: __device__ globals)
__device__ float g_q[Mrows*Dq];
__device__ float g_k[Mrows*Dq];
__device__ float g_v[Mrows*Dq];
__device__ float g_a[Mrows*Dq];
__device__ uint2 g_kp[(size_t)64*NTILES*2048];     // packed K fragments (hi only)
__device__ uint2 g_vp[(size_t)64*NTILES*2048];     // packed V fragments (hi only)
__device__ uint4 g_xp[(size_t)Mrows*Dq/4];          // packed x   (A layout)
__device__ uint4 g_ap[(size_t)Mrows*Dq/4];          // packed attn out (A layout)
__device__ uint4 g_wq[(size_t)Dq*Dq/4];             // packed weights (B layout)
__device__ uint4 g_wk[(size_t)Dq*Dq/4];
__device__ uint4 g_wv[(size_t)Dq*Dq/4];
__device__ uint4 g_wo[(size_t)Dq*Dq/4];

__device__ __forceinline__ uint32_t f2tf(float f) {
    uint32_t u;
    asm("cvt.rna.tf32.f32 %0, %1;" : "=r"(u) : "f"(f));
    return u;
}
__device__ __forceinline__ float ex2(float x) {
    float r;
    asm("ex2.approx.f32 %0, %1;" : "=f"(r) : "f"(x));
    return r;
}
__device__ __forceinline__ void mma_tf32(float* c, uint4 a, uint32_t b0, uint32_t b1) {
    asm volatile("mma.sync.aligned.m16n8k8.row.col.f32.tf32.tf32.f32 "
        "{%0,%1,%2,%3}, {%4,%5,%6,%7}, {%8,%9}, {%0,%1,%2,%3};"
        : "+f"(c[0]), "+f"(c[1]), "+f"(c[2]), "+f"(c[3])
        : "r"(a.x), "r"(a.y), "r"(a.z), "r"(a.w), "r"(b0), "r"(b1));
}
__device__ __forceinline__ void cp16(uint32_t sa, const void* g) {
    asm volatile("cp.async.cg.shared.global [%0], [%1], 16;" :: "r"(sa), "l"(g));
}

// ---------------------------------------------------------------------------
// Pack a float matrix [R x 1024] into A-layout fragment tiles (TF32).
// ---------------------------------------------------------------------------
__global__ void __launch_bounds__(256) pack_a(const float* __restrict__ A,
                                              uint32_t* __restrict__ out)
{
    const int rb = blockIdx.x, ch = blockIdx.y, tid = threadIdx.x;
    const int rbase = tid >> 3, kc = (tid & 7) << 2;
    const int ks = (tid & 7) >> 1, hi = tid & 1;
    uint32_t* ot = out + ((size_t)rb * NCH + ch) * 4096;
    const float* Ab = A + ((size_t)rb * 128) * Dq + ch * 32;
    #pragma unroll
    for (int i = 0; i < 4; ++i) {
        int r = rbase + 32*i;
        float4 f4 = *reinterpret_cast<const float4*>(Ab + (size_t)r * Dq + kc);
        const float* f = &f4.x;
        int mt = r >> 4, rr = r & 15;
        int w = (rr >> 3) + (hi << 1);
        int base = (mt*4 + ks) * 32;
        int l0 = (rr & 7) << 2;
        #pragma unroll
        for (int j = 0; j < 4; ++j)
            ot[(base + ((l0 + j) ^ (ks << 1))) * 4 + w] = f2tf(f[j]);
    }
}

// ---------------------------------------------------------------------------
// Pack the 4 weight matrices into B-layout fragment tiles.
// ---------------------------------------------------------------------------
__global__ void __launch_bounds__(256) pack_w(const float* __restrict__ w0,
                                              const float* __restrict__ w1,
                                              const float* __restrict__ w2,
                                              const float* __restrict__ w3,
                                              uint32_t* __restrict__ o0,
                                              uint32_t* __restrict__ o1,
                                              uint32_t* __restrict__ o2,
                                              uint32_t* __restrict__ o3)
{
    const float* W = (blockIdx.z == 0) ? w0 : (blockIdx.z == 1) ? w1
                    : (blockIdx.z == 2) ? w2 : w3;
    uint32_t* O = (blockIdx.z == 0) ? o0 : (blockIdx.z == 1) ? o1
                 : (blockIdx.z == 2) ? o2 : o3;
    const int nb = blockIdx.x, ch = blockIdx.y, tid = threadIdx.x;
    const int rbase = tid >> 3, kc = (tid & 7) << 2;
    const int ks = (tid & 7) >> 1, hi = tid & 1;
    uint32_t* ot = O + ((size_t)nb * NCH + ch) * 4096;
    const float* Wb = W + ((size_t)nb * 128) * Dq + ch * 32;
    #pragma unroll
    for (int i = 0; i < 4; ++i) {
        int n = rbase + 32*i;
        float4 f4 = *reinterpret_cast<const float4*>(Wb + (size_t)n * Dq + kc);
        const float* f = &f4.x;
        int nt = n >> 3, gg = n & 7;
        int w = ((nt & 1) << 1) + hi;
        int base = ((nt >> 1)*4 + ks) * 32;
        int l0 = gg << 2;
        #pragma unroll
        for (int j = 0; j < 4; ++j)
            ot[(base + ((l0 + j) ^ (ks << 1))) * 4 + w] = f2tf(f[j]);
    }
}

// ---------------------------------------------------------------------------
// TF32 GEMM on pre-packed operands (unchanged from R6/R7).
// ---------------------------------------------------------------------------
extern __shared__ uint32_t gsm[];
__global__ void __launch_bounds__(256, 2) gemm_packed(const uint4* __restrict__ Ap,
                                                      const uint4* __restrict__ Bp,
                                                      float* __restrict__ C, int M)
{
    const int tid = threadIdx.x;
    const int lane = tid & 31, wid = tid >> 5;
    const int wm = wid >> 1, wn = wid & 1;
    const int g = lane >> 2, t = lane & 3;
    const size_t tA0 = (size_t)blockIdx.y * NCH;
    const size_t tB0 = (size_t)blockIdx.x * NCH;
    const uint32_t sbase = (uint32_t)__cvta_generic_to_shared(gsm);

    float acc[2][8][4];
    #pragma unroll
    for (int mt = 0; mt < 2; ++mt)
        #pragma unroll
        for (int j = 0; j < 8; ++j)
            #pragma unroll
            for (int e = 0; e < 4; ++e) acc[mt][j][e] = 0.f;

    auto prefetch = [&](int ch, int s) {
        const uint4* ga = Ap + (tA0 + ch) * 1024 + tid;
        const uint4* gb = Bp + (tB0 + ch) * 1024 + tid;
        uint32_t sA = sbase + s * 32768;
        uint32_t sB = sA + 16384;
        #pragma unroll
        for (int i = 0; i < 4; ++i)
            cp16(sA + (tid + (i << 8)) * 16, ga + (i << 8));
        #pragma unroll
        for (int i = 0; i < 4; ++i)
            cp16(sB + (tid + (i << 8)) * 16, gb + (i << 8));
    };

    prefetch(0, 0);
    asm volatile("cp.async.commit_group;");
    prefetch(1, 1);
    asm volatile("cp.async.commit_group;");

    for (int ch = 0; ch < NCH; ++ch) {
        const int s = ch % 3;
        asm volatile("cp.async.wait_group 1;");
        __syncthreads();
        if (ch + 2 < NCH) prefetch(ch + 2, (ch + 2) % 3);
        asm volatile("cp.async.commit_group;");

        const uint32_t* As = gsm + s * 8192;
        const uint32_t* Bs = As + 4096;
        #pragma unroll
        for (int ks = 0; ks < 4; ++ks) {
            uint4 af[2], bf[4];
            const int sl = lane ^ (ks << 1);
            #pragma unroll
            for (int mt = 0; mt < 2; ++mt)
                af[mt] = *reinterpret_cast<const uint4*>(
                    &As[(((wm*2 + mt)*4 + ks)*32 + sl) * 4]);
            #pragma unroll
            for (int p = 0; p < 4; ++p)
                bf[p] = *reinterpret_cast<const uint4*>(
                    &Bs[(((wn*4 + p)*4 + ks)*32 + sl) * 4]);
            #pragma unroll
            for (int mt = 0; mt < 2; ++mt)
                #pragma unroll
                for (int p = 0; p < 4; ++p) {
                    mma_tf32(acc[mt][2*p],   af[mt], bf[p].x, bf[p].y);
                    mma_tf32(acc[mt][2*p+1], af[mt], bf[p].z, bf[p].w);
                }
        }
    }

    const int bm = blockIdx.y * 128, bn = blockIdx.x * 128;
    #pragma unroll
    for (int mt = 0; mt < 2; ++mt) {
        #pragma unroll
        for (int j = 0; j < 8; ++j) {
            int m = bm + wm*32 + mt*16 + g;
            int n = bn + wn*64 + j*8 + t*2;
            *reinterpret_cast<float2*>(C + (size_t)m * Dq + n)       = make_float2(acc[mt][j][0], acc[mt][j][1]);
            *reinterpret_cast<float2*>(C + (size_t)(m + 8) * Dq + n) = make_float2(acc[mt][j][2], acc[mt][j][3]);
        }
    }
}

// ---------------------------------------------------------------------------
// Pack K (hi only now) and V (hi, transposed) into mma-fragment order.
// ---------------------------------------------------------------------------
__global__ void __launch_bounds__(256) pack_kv(const float* __restrict__ Kg,
                                               const float* __restrict__ Vg,
                                               uint2* __restrict__ kp,
                                               uint2* __restrict__ vp)
{
    __shared__ float Vst[64*68];
    const int j = blockIdx.x, bh = blockIdx.y;
    const int b = bh >> 4, h = bh & 15;
    const size_t base = (size_t)b * Sq * Dq + (size_t)h * DKq;
    const int key0 = j << 6;
    const int tid = threadIdx.x;
    uint2* kpt = kp + ((size_t)bh * NTILES + j) * 2048;
    uint2* vpt = vp + ((size_t)bh * NTILES + j) * 2048;

    #pragma unroll
    for (int i = 0; i < 2; ++i) {
        int ta = tid + (i << 8);
        int kk = ta & 7, key = ta >> 3;
        const float* kq = Kg + base + (size_t)(key0 + key) * Dq + kk*8;
        float4 f0 = *reinterpret_cast<const float4*>(kq);
        float4 f1 = *reinterpret_cast<const float4*>(kq + 4);
        const float* p0 = &f0.x; const float* p1 = &f1.x;
        int sw = 4*(kk ^ (key & 7));
        int txor = (key >> 3) & 3;
        #pragma unroll
        for (int tt = 0; tt < 4; ++tt)
            kpt[key*32 + sw + (tt ^ txor)] = make_uint2(f2tf(p0[tt]), f2tf(p1[tt]));
    }
    #pragma unroll
    for (int i = 0; i < 4; ++i) {
        int id = tid + (i << 8);
        int rr = id >> 4, c4 = (id & 15) << 2;
        *reinterpret_cast<float4*>(Vst + rr*68 + c4) =
            *reinterpret_cast<const float4*>(Vg + base + (size_t)(key0 + rr) * Dq + c4);
    }
    __syncthreads();
    #pragma unroll
    for (int i = 0; i < 2; ++i) {
        int dk = tid & 63, kk = (tid >> 6) + (i << 2);
        float f[8];
        #pragma unroll
        for (int r = 0; r < 8; ++r) f[r] = Vst[(8*kk + r)*68 + dk];
        int sw = 4*(kk ^ (dk & 7));
        int txor = (dk >> 3) & 3;
        #pragma unroll
        for (int tt = 0; tt < 4; ++tt)
            vpt[dk*32 + sw + (tt ^ txor)] = make_uint2(f2tf(f[tt]), f2tf(f[tt+4]));
    }
}

// ---------------------------------------------------------------------------
// Tensor-core causal flash attention.
// Block = 256 q-rows; 512 threads = 16 warps x m16; n=64 tiles.
// K and V both single-rounded TF32 (uint2 fragments); QK = 8 mmas/tile/warp/n8-col.
// Smem (u32): QA 0..16K | PA 16K..32K | KB 32K+s*4K | VB 40K+s*4K = 192KB.
// ---------------------------------------------------------------------------
extern __shared__ uint32_t sm_u[];
__global__ void __launch_bounds__(512, 1) attn_tc(const float* __restrict__ Qg,
                                                  const uint2* __restrict__ kp,
                                                  const uint2* __restrict__ vp,
                                                  float* __restrict__ Og)
{
    uint4* QA = reinterpret_cast<uint4*>(sm_u);              // 4096 u4 (64KB)
    uint4* PA = reinterpret_cast<uint4*>(sm_u + 16384);      // 4096 u4 (64KB)
    const uint32_t sbase = (uint32_t)__cvta_generic_to_shared(sm_u);

    const int tid  = threadIdx.x;
    const int lane = tid & 31, w = tid >> 5;                 // w: 0..15
    const int g = lane >> 2, t = lane & 3;
    const int qb = 7 - blockIdx.x;                           // heavy blocks first
    const int bh = blockIdx.y;
    const int b = bh >> 4, h = bh & 15;
    const size_t base = (size_t)b * Sq * Dq + (size_t)h * DKq;
    const int q0 = qb * 256;
    const float qsc = 0.125f * 1.44269504f;                  // fold log2e

    // ---- Build QA once (256 rows) ----
    #pragma unroll
    for (int i = 0; i < 2; ++i) {
        int ta = tid + (i << 9);
        int kk = ta & 7, gg = (ta >> 3) & 7, sl = ta >> 6;   // sl: 0..15
        int row = q0 + sl*16 + gg;
        const float* p0 = Qg + base + (size_t)row * Dq + kk*8;
        const float* p1 = p0 + 8*Dq;
        float4 a0 = *reinterpret_cast<const float4*>(p0);
        float4 a1 = *reinterpret_cast<const float4*>(p0 + 4);
        float4 b0 = *reinterpret_cast<const float4*>(p1);
        float4 b1 = *reinterpret_cast<const float4*>(p1 + 4);
        const float* fa0 = &a0.x; const float* fa1 = &a1.x;
        const float* fb0 = &b0.x; const float* fb1 = &b1.x;
        #pragma unroll
        for (int tt = 0; tt < 4; ++tt) {
            QA[sl*256 + gg*32 + 4*(kk ^ gg) + tt] =
                make_uint4(f2tf(fa0[tt]*qsc), f2tf(fb0[tt]*qsc),
                           f2tf(fa1[tt]*qsc), f2tf(fb1[tt]*qsc));
        }
    }

    auto prefetch = [&](int j, int s) {
        const uint4* kpt4 = reinterpret_cast<const uint4*>(kp) + ((size_t)bh * NTILES + j) * 1024;
        const uint4* vpt4 = reinterpret_cast<const uint4*>(vp) + ((size_t)bh * NTILES + j) * 1024;
        uint32_t sK = sbase + (32768 + s * 4096) * 4;
        uint32_t sV = sbase + (40960 + s * 4096) * 4;
        #pragma unroll
        for (int i = 0; i < 2; ++i)
            cp16(sK + (tid + (i << 9)) * 16, kpt4 + tid + (i << 9));
        #pragma unroll
        for (int i = 0; i < 2; ++i)
            cp16(sV + (tid + (i << 9)) * 16, vpt4 + tid + (i << 9));
    };

    const int row_hi = q0 + w*16 + 15;
    float mst0 = LNEG, mst1 = LNEG, lst0 = 0.f, lst1 = 0.f;
    float Od[8][4];
    #pragma unroll
    for (int n8 = 0; n8 < 8; ++n8)
        #pragma unroll
        for (int e = 0; e < 4; ++e) Od[n8][e] = 0.f;

    const int jmax = 4*qb + 3;
    prefetch(0, 0);
    asm volatile("cp.async.commit_group;");

    for (int j = 0; j <= jmax; ++j) {
        const int s = j & 1;
        const int key0 = j << 6;
        if (j + 1 <= jmax) prefetch(j + 1, s ^ 1);
        asm volatile("cp.async.commit_group;");
        asm volatile("cp.async.wait_group 1;");
        __syncthreads();

        if (key0 <= row_hi) {
            const uint2* KBs = reinterpret_cast<const uint2*>(sm_u + 32768 + s * 4096);
            const uint2* VBs = reinterpret_cast<const uint2*>(sm_u + 40960 + s * 4096);

            // ---- QK^T (K hi only) ----
            float acc[8][4];
            #pragma unroll
            for (int n8 = 0; n8 < 8; ++n8)
                #pragma unroll
                for (int e = 0; e < 4; ++e) acc[n8][e] = 0.f;

            #pragma unroll
            for (int kk = 0; kk < 8; ++kk) {
                uint4 aq = QA[w*256 + g*32 + 4*(kk ^ g) + t];
                #pragma unroll
                for (int n8 = 0; n8 < 8; ++n8) {
                    uint2 kb = KBs[(8*n8 + g)*32 + 4*(kk ^ g) + (t ^ (n8 & 3))];
                    mma_tf32(acc[n8], aq, kb.x, kb.y);
                }
            }
            // ---- causal mask (tiles that can clip this warp) ----
            if (key0 + 63 > q0 + w*16) {
                int r0 = q0 + w*16 + g, r1 = r0 + 8;
                #pragma unroll
                for (int n8 = 0; n8 < 8; ++n8) {
                    int c0 = key0 + 8*n8 + 2*t, c1 = c0 + 1;
                    if (c0 > r0) acc[n8][0] = LNEG;
                    if (c1 > r0) acc[n8][1] = LNEG;
                    if (c0 > r1) acc[n8][2] = LNEG;
                    if (c1 > r1) acc[n8][3] = LNEG;
                }
            }
            // ---- online softmax (log2 domain) ----
            float t0 = LNEG, t1 = LNEG;
            #pragma unroll
            for (int n8 = 0; n8 < 8; ++n8) {
                t0 = fmaxf(t0, fmaxf(acc[n8][0], acc[n8][1]));
                t1 = fmaxf(t1, fmaxf(acc[n8][2], acc[n8][3]));
            }
            t0 = fmaxf(t0, __shfl_xor_sync(0xffffffffu, t0, 1));
            t0 = fmaxf(t0, __shfl_xor_sync(0xffffffffu, t0, 2));
            t1 = fmaxf(t1, __shfl_xor_sync(0xffffffffu, t1, 1));
            t1 = fmaxf(t1, __shfl_xor_sync(0xffffffffu, t1, 2));
            float m0n = fmaxf(mst0, t0), m1n = fmaxf(mst1, t1);
            float c0 = ex2(mst0 - m0n), c1 = ex2(mst1 - m1n);
            float s0 = 0.f, s1 = 0.f;

            int d0 = 2*t, d1 = 2*t + 1;
            int tw0 = d0 & 3, sl0 = (d0 >> 2) << 1;
            int tw1 = d1 & 3, sl1 = (d1 >> 2) << 1;
            #pragma unroll
            for (int n8 = 0; n8 < 8; ++n8) {
                float p00 = ex2(acc[n8][0] - m0n);
                float p01 = ex2(acc[n8][1] - m0n);
                float p10 = ex2(acc[n8][2] - m1n);
                float p11 = ex2(acc[n8][3] - m1n);
                s0 += p00 + p01;
                s1 += p10 + p11;
                uint32_t* pw = reinterpret_cast<uint32_t*>(&PA[w*256 + g*32 + 4*(n8 ^ g)]);
                pw[tw0*4 + sl0]     = f2tf(p00);
                pw[tw0*4 + sl0 + 1] = f2tf(p10);
                pw[tw1*4 + sl1]     = f2tf(p01);
                pw[tw1*4 + sl1 + 1] = f2tf(p11);
            }
            lst0 = lst0 * c0 + s0;       // per-lane partials; c row-uniform
            lst1 = lst1 * c1 + s1;
            mst0 = m0n; mst1 = m1n;
            #pragma unroll
            for (int n8 = 0; n8 < 8; ++n8) {
                Od[n8][0] *= c0; Od[n8][1] *= c0;
                Od[n8][2] *= c1; Od[n8][3] *= c1;
            }
            __syncwarp();

            // ---- P @ V (V hi only) ----
            #pragma unroll
            for (int kk = 0; kk < 8; ++kk) {
                uint4 pa = PA[w*256 + g*32 + 4*(kk ^ g) + t];
                #pragma unroll
                for (int n8 = 0; n8 < 8; ++n8) {
                    uint2 vb = VBs[(8*n8 + g)*32 + 4*(kk ^ g) + (t ^ (n8 & 3))];
                    mma_tf32(Od[n8], pa, vb.x, vb.y);
                }
            }
        }
        __syncthreads();                 // stage s free for prefetch at j+1
    }

    // ---- epilogue: reduce per-lane l partials across the 4 t-lanes ----
    lst0 += __shfl_xor_sync(0xffffffffu, lst0, 1);
    lst0 += __shfl_xor_sync(0xffffffffu, lst0, 2);
    lst1 += __shfl_xor_sync(0xffffffffu, lst1, 1);
    lst1 += __shfl_xor_sync(0xffffffffu, lst1, 2);
    float i0 = 1.f / lst0, i1 = 1.f / lst1;
    int r0 = q0 + w*16 + g;
    #pragma unroll
    for (int n8 = 0; n8 < 8; ++n8) {
        int col = h*64 + 8*n8 + 2*t;
        size_t o0 = (size_t)((size_t)b * Sq + r0) * Dq + col;
        *reinterpret_cast<float2*>(Og + o0)          = make_float2(Od[n8][0]*i0, Od[n8][1]*i0);
        *reinterpret_cast<float2*>(Og + o0 + 8*Dq)   = make_float2(Od[n8][2]*i1, Od[n8][3]*i1);
    }
}

// ---------------------------------------------------------------------------
extern "C" void kernel_launch(void* const* d_in, const int* in_sizes, int n_in,
                              void* d_out, int out_size)
{
    const float* x  = (const float*)d_in[0];
    const float* wq = (const float*)d_in[1];
    const float* wk = (const float*)d_in[2];
    const float* wv = (const float*)d_in[3];
    const float* wo = (const float*)d_in[4];
    float* out = (float*)d_out;

    float *q, *k, *v, *a;
    uint4 *xp, *ap, *pwq, *pwk, *pwv, *pwo;
    uint2 *kpp, *vpp;
    cudaGetSymbolAddress((void**)&q,   g_q);
    cudaGetSymbolAddress((void**)&k,   g_k);
    cudaGetSymbolAddress((void**)&v,   g_v);
    cudaGetSymbolAddress((void**)&a,   g_a);
    cudaGetSymbolAddress((void**)&kpp, g_kp);
    cudaGetSymbolAddress((void**)&vpp, g_vp);
    cudaGetSymbolAddress((void**)&xp,  g_xp);
    cudaGetSymbolAddress((void**)&ap,  g_ap);
    cudaGetSymbolAddress((void**)&pwq, g_wq);
    cudaGetSymbolAddress((void**)&pwk, g_wk);
    cudaGetSymbolAddress((void**)&pwv, g_wv);
    cudaGetSymbolAddress((void**)&pwo, g_wo);

    pack_a<<<dim3(Mrows/128, NCH), 256>>>(x, (uint32_t*)xp);
    pack_w<<<dim3(8, NCH, 4), 256>>>(wq, wk, wv, wo,
                                     (uint32_t*)pwq, (uint32_t*)pwk,
                                     (uint32_t*)pwv, (uint32_t*)pwo);

    int smem_gemm = 98304;
    cudaFuncSetAttribute(gemm_packed, cudaFuncAttributeMaxDynamicSharedMemorySize, smem_gemm);
    dim3 gg(Dq/128, Mrows/128);
    gemm_packed<<<gg, 256, smem_gemm>>>(xp, pwq, q, Mrows);
    gemm_packed<<<gg, 256, smem_gemm>>>(xp, pwk, k, Mrows);
    gemm_packed<<<gg, 256, smem_gemm>>>(xp, pwv, v, Mrows);

    pack_kv<<<dim3(NTILES, 64), 256>>>(k, v, kpp, vpp);

    int smem_attn = 196608;   // 192KB: QA 64 | PA 64 | KB 2x16 | VB 2x16
    cudaFuncSetAttribute(attn_tc, cudaFuncAttributeMaxDynamicSharedMemorySize, smem_attn);
    attn_tc<<<dim3(8, 64), 512, smem_attn>>>(q, kpp, vpp, a);

    pack_a<<<dim3(Mrows/128, NCH), 256>>>(a, (uint32_t*)ap);
    gemm_packed<<<gg, 256, smem_gemm>>>(ap, pwo, out, Mrows);
}

// round 10
// speedup vs baseline: 7.2902x; 1.0893x over previous
#include <cuda_runtime.h>
#include <cstdint>
#include <cstddef>

#define Bq 4
#define Sq 2048
#define Dq 1024
#define Hq 16
#define DKq 64
#define Mrows (Bq*Sq)
#define NTILES 32          // key tiles per (b,h)
#define NCH 32             // K chunks per GEMM (K=1024 / 32)
#define LNEG -1e30f

// Scratch (allocation-free rule: __device__ globals)
__device__ float g_q[Mrows*Dq];
__device__ uint2 g_kp[(size_t)64*NTILES*2048];     // packed K fragments (hi only)
__device__ uint2 g_vp[(size_t)64*NTILES*2048];     // packed V fragments (hi only)
__device__ uint4 g_xp[(size_t)Mrows*Dq/4];          // packed x   (A layout)
__device__ uint4 g_ap[(size_t)Mrows*Dq/4];          // packed attn out (A layout)
__device__ uint4 g_wq[(size_t)Dq*Dq/4];             // packed weights (B layout)
__device__ uint4 g_wk[(size_t)Dq*Dq/4];
__device__ uint4 g_wv[(size_t)Dq*Dq/4];
__device__ uint4 g_wo[(size_t)Dq*Dq/4];

__device__ __forceinline__ uint32_t f2tf(float f) {
    uint32_t u;
    asm("cvt.rna.tf32.f32 %0, %1;" : "=r"(u) : "f"(f));
    return u;
}
__device__ __forceinline__ float ex2(float x) {
    float r;
    asm("ex2.approx.f32 %0, %1;" : "=f"(r) : "f"(x));
    return r;
}
__device__ __forceinline__ void mma_tf32(float* c, uint4 a, uint32_t b0, uint32_t b1) {
    asm volatile("mma.sync.aligned.m16n8k8.row.col.f32.tf32.tf32.f32 "
        "{%0,%1,%2,%3}, {%4,%5,%6,%7}, {%8,%9}, {%0,%1,%2,%3};"
        : "+f"(c[0]), "+f"(c[1]), "+f"(c[2]), "+f"(c[3])
        : "r"(a.x), "r"(a.y), "r"(a.z), "r"(a.w), "r"(b0), "r"(b1));
}
__device__ __forceinline__ void cp16(uint32_t sa, const void* g) {
    asm volatile("cp.async.cg.shared.global [%0], [%1], 16;" :: "r"(sa), "l"(g));
}

// ---------------------------------------------------------------------------
// Pack a float matrix [R x 1024] into A-layout fragment tiles (TF32).
// ---------------------------------------------------------------------------
__global__ void __launch_bounds__(256) pack_a(const float* __restrict__ A,
                                              uint32_t* __restrict__ out)
{
    const int rb = blockIdx.x, ch = blockIdx.y, tid = threadIdx.x;
    const int rbase = tid >> 3, kc = (tid & 7) << 2;
    const int ks = (tid & 7) >> 1, hi = tid & 1;
    uint32_t* ot = out + ((size_t)rb * NCH + ch) * 4096;
    const float* Ab = A + ((size_t)rb * 128) * Dq + ch * 32;
    #pragma unroll
    for (int i = 0; i < 4; ++i) {
        int r = rbase + 32*i;
        float4 f4 = *reinterpret_cast<const float4*>(Ab + (size_t)r * Dq + kc);
        const float* f = &f4.x;
        int mt = r >> 4, rr = r & 15;
        int w = (rr >> 3) + (hi << 1);
        int base = (mt*4 + ks) * 32;
        int l0 = (rr & 7) << 2;
        #pragma unroll
        for (int j = 0; j < 4; ++j)
            ot[(base + ((l0 + j) ^ (ks << 1))) * 4 + w] = f2tf(f[j]);
    }
}

// ---------------------------------------------------------------------------
// Pack the 4 weight matrices into B-layout fragment tiles.
// ---------------------------------------------------------------------------
__global__ void __launch_bounds__(256) pack_w(const float* __restrict__ w0,
                                              const float* __restrict__ w1,
                                              const float* __restrict__ w2,
                                              const float* __restrict__ w3,
                                              uint32_t* __restrict__ o0,
                                              uint32_t* __restrict__ o1,
                                              uint32_t* __restrict__ o2,
                                              uint32_t* __restrict__ o3)
{
    const float* W = (blockIdx.z == 0) ? w0 : (blockIdx.z == 1) ? w1
                    : (blockIdx.z == 2) ? w2 : w3;
    uint32_t* O = (blockIdx.z == 0) ? o0 : (blockIdx.z == 1) ? o1
                 : (blockIdx.z == 2) ? o2 : o3;
    const int nb = blockIdx.x, ch = blockIdx.y, tid = threadIdx.x;
    const int rbase = tid >> 3, kc = (tid & 7) << 2;
    const int ks = (tid & 7) >> 1, hi = tid & 1;
    uint32_t* ot = O + ((size_t)nb * NCH + ch) * 4096;
    const float* Wb = W + ((size_t)nb * 128) * Dq + ch * 32;
    #pragma unroll
    for (int i = 0; i < 4; ++i) {
        int n = rbase + 32*i;
        float4 f4 = *reinterpret_cast<const float4*>(Wb + (size_t)n * Dq + kc);
        const float* f = &f4.x;
        int nt = n >> 3, gg = n & 7;
        int w = ((nt & 1) << 1) + hi;
        int base = ((nt >> 1)*4 + ks) * 32;
        int l0 = gg << 2;
        #pragma unroll
        for (int j = 0; j < 4; ++j)
            ot[(base + ((l0 + j) ^ (ks << 1))) * 4 + w] = f2tf(f[j]);
    }
}

// ---------------------------------------------------------------------------
// Fused QKV TF32 GEMM on pre-packed operands. grid (8, 64, 3).
// z=0: C=x@Wq^T -> float g_q.  z=1: x@Wk^T -> packed kp.  z=2: x@Wv^T -> vp.
// K/V epilogues stage into pipeline smem (inverse pack_kv maps), copy out
// coalesced. Smem: 3 x (16KB A + 16KB B) = 96KB (staging reuses it).
// ---------------------------------------------------------------------------
extern __shared__ uint32_t gsm[];
__global__ void __launch_bounds__(256, 2) gemm_qkv(const uint4* __restrict__ Ap,
                                                   const uint4* __restrict__ Bq_,
                                                   const uint4* __restrict__ Bk_,
                                                   const uint4* __restrict__ Bv_,
                                                   float* __restrict__ Cq,
                                                   uint32_t* __restrict__ kp32,
                                                   uint32_t* __restrict__ vp32)
{
    const int tid = threadIdx.x;
    const int lane = tid & 31, wid = tid >> 5;
    const int wm = wid >> 1, wn = wid & 1;
    const int g = lane >> 2, t = lane & 3;
    const int z = blockIdx.z;
    const uint4* Bp = (z == 0) ? Bq_ : (z == 1) ? Bk_ : Bv_;
    const size_t tA0 = (size_t)blockIdx.y * NCH;
    const size_t tB0 = (size_t)blockIdx.x * NCH;
    const uint32_t sbase = (uint32_t)__cvta_generic_to_shared(gsm);

    float acc[2][8][4];
    #pragma unroll
    for (int mt = 0; mt < 2; ++mt)
        #pragma unroll
        for (int j = 0; j < 8; ++j)
            #pragma unroll
            for (int e = 0; e < 4; ++e) acc[mt][j][e] = 0.f;

    auto prefetch = [&](int ch, int s) {
        const uint4* ga = Ap + (tA0 + ch) * 1024 + tid;
        const uint4* gb = Bp + (tB0 + ch) * 1024 + tid;
        uint32_t sA = sbase + s * 32768;
        uint32_t sB = sA + 16384;
        #pragma unroll
        for (int i = 0; i < 4; ++i)
            cp16(sA + (tid + (i << 8)) * 16, ga + (i << 8));
        #pragma unroll
        for (int i = 0; i < 4; ++i)
            cp16(sB + (tid + (i << 8)) * 16, gb + (i << 8));
    };

    prefetch(0, 0);
    asm volatile("cp.async.commit_group;");
    prefetch(1, 1);
    asm volatile("cp.async.commit_group;");

    for (int ch = 0; ch < NCH; ++ch) {
        const int s = ch % 3;
        asm volatile("cp.async.wait_group 1;");
        __syncthreads();
        if (ch + 2 < NCH) prefetch(ch + 2, (ch + 2) % 3);
        asm volatile("cp.async.commit_group;");

        const uint32_t* As = gsm + s * 8192;
        const uint32_t* Bs = As + 4096;
        #pragma unroll
        for (int ks = 0; ks < 4; ++ks) {
            uint4 af[2], bf[4];
            const int sl = lane ^ (ks << 1);
            #pragma unroll
            for (int mt = 0; mt < 2; ++mt)
                af[mt] = *reinterpret_cast<const uint4*>(
                    &As[(((wm*2 + mt)*4 + ks)*32 + sl) * 4]);
            #pragma unroll
            for (int p = 0; p < 4; ++p)
                bf[p] = *reinterpret_cast<const uint4*>(
                    &Bs[(((wn*4 + p)*4 + ks)*32 + sl) * 4]);
            #pragma unroll
            for (int mt = 0; mt < 2; ++mt)
                #pragma unroll
                for (int p = 0; p < 4; ++p) {
                    mma_tf32(acc[mt][2*p],   af[mt], bf[p].x, bf[p].y);
                    mma_tf32(acc[mt][2*p+1], af[mt], bf[p].z, bf[p].w);
                }
        }
    }

    const int bm = blockIdx.y * 128, bn = blockIdx.x * 128;

    if (z == 0) {
        // Q: plain float epilogue
        #pragma unroll
        for (int mt = 0; mt < 2; ++mt)
            #pragma unroll
            for (int j = 0; j < 8; ++j) {
                int m = bm + wm*32 + mt*16 + g;
                int n = bn + wn*64 + j*8 + t*2;
                *reinterpret_cast<float2*>(Cq + (size_t)m * Dq + n)       = make_float2(acc[mt][j][0], acc[mt][j][1]);
                *reinterpret_cast<float2*>(Cq + (size_t)(m + 8) * Dq + n) = make_float2(acc[mt][j][2], acc[mt][j][3]);
            }
        return;
    }

    // K/V: stage packed-fragment layout into smem, then coalesced copy
    asm volatile("cp.async.wait_group 0;");
    __syncthreads();          // pipeline dead; gsm reusable

    #pragma unroll
    for (int mt = 0; mt < 2; ++mt)
        #pragma unroll
        for (int j = 0; j < 8; ++j)
            #pragma unroll
            for (int e = 0; e < 4; ++e) {
                int rloc = wm*32 + mt*16 + g + ((e >> 1) << 3);   // 0..127
                int nloc = wn*64 + j*8 + 2*t + (e & 1);           // 0..127
                int rh = rloc >> 6, ch2 = nloc >> 6;
                int idx;
                if (z == 1) {
                    int keyl = rloc & 63, dkl = nloc & 63;
                    int kk2 = dkl >> 3, rr2 = dkl & 7;
                    idx = (keyl*32 + 4*(kk2 ^ (keyl & 7)) + ((rr2 & 3) ^ ((keyl >> 3) & 3)))*2 + (rr2 >> 2);
                } else {
                    int keyl = rloc & 63, dkl = nloc & 63;
                    int kk3 = keyl >> 3, rr3 = keyl & 7;
                    idx = (dkl*32 + 4*(kk3 ^ (dkl & 7)) + ((rr3 & 3) ^ ((dkl >> 3) & 3)))*2 + (rr3 >> 2);
                }
                gsm[(rh*2 + ch2)*4096 + idx] = f2tf(acc[mt][j][e]);
            }
    __syncthreads();

    uint32_t* dstb = (z == 1) ? kp32 : vp32;
    const int b = bm >> 11, jt0 = (bm & 2047) >> 6, h0 = bn >> 6;
    #pragma unroll
    for (int qd = 0; qd < 4; ++qd) {
        int rh = qd >> 1, ch2 = qd & 1;
        int bh = b*16 + h0 + ch2;
        int jt = jt0 + rh;
        uint4* dst = reinterpret_cast<uint4*>(dstb) + ((size_t)bh*NTILES + jt) * 1024;
        const uint4* src = reinterpret_cast<const uint4*>(gsm) + qd * 1024;
        #pragma unroll
        for (int i = 0; i < 4; ++i)
            dst[tid + (i << 8)] = src[tid + (i << 8)];
    }
}

// ---------------------------------------------------------------------------
// TF32 GEMM on pre-packed operands (final O-projection), float epilogue.
// ---------------------------------------------------------------------------
__global__ void __launch_bounds__(256, 2) gemm_packed(const uint4* __restrict__ Ap,
                                                      const uint4* __restrict__ Bp,
                                                      float* __restrict__ C)
{
    const int tid = threadIdx.x;
    const int lane = tid & 31, wid = tid >> 5;
    const int wm = wid >> 1, wn = wid & 1;
    const int g = lane >> 2, t = lane & 3;
    const size_t tA0 = (size_t)blockIdx.y * NCH;
    const size_t tB0 = (size_t)blockIdx.x * NCH;
    const uint32_t sbase = (uint32_t)__cvta_generic_to_shared(gsm);

    float acc[2][8][4];
    #pragma unroll
    for (int mt = 0; mt < 2; ++mt)
        #pragma unroll
        for (int j = 0; j < 8; ++j)
            #pragma unroll
            for (int e = 0; e < 4; ++e) acc[mt][j][e] = 0.f;

    auto prefetch = [&](int ch, int s) {
        const uint4* ga = Ap + (tA0 + ch) * 1024 + tid;
        const uint4* gb = Bp + (tB0 + ch) * 1024 + tid;
        uint32_t sA = sbase + s * 32768;
        uint32_t sB = sA + 16384;
        #pragma unroll
        for (int i = 0; i < 4; ++i)
            cp16(sA + (tid + (i << 8)) * 16, ga + (i << 8));
        #pragma unroll
        for (int i = 0; i < 4; ++i)
            cp16(sB + (tid + (i << 8)) * 16, gb + (i << 8));
    };

    prefetch(0, 0);
    asm volatile("cp.async.commit_group;");
    prefetch(1, 1);
    asm volatile("cp.async.commit_group;");

    for (int ch = 0; ch < NCH; ++ch) {
        const int s = ch % 3;
        asm volatile("cp.async.wait_group 1;");
        __syncthreads();
        if (ch + 2 < NCH) prefetch(ch + 2, (ch + 2) % 3);
        asm volatile("cp.async.commit_group;");

        const uint32_t* As = gsm + s * 8192;
        const uint32_t* Bs = As + 4096;
        #pragma unroll
        for (int ks = 0; ks < 4; ++ks) {
            uint4 af[2], bf[4];
            const int sl = lane ^ (ks << 1);
            #pragma unroll
            for (int mt = 0; mt < 2; ++mt)
                af[mt] = *reinterpret_cast<const uint4*>(
                    &As[(((wm*2 + mt)*4 + ks)*32 + sl) * 4]);
            #pragma unroll
            for (int p = 0; p < 4; ++p)
                bf[p] = *reinterpret_cast<const uint4*>(
                    &Bs[(((wn*4 + p)*4 + ks)*32 + sl) * 4]);
            #pragma unroll
            for (int mt = 0; mt < 2; ++mt)
                #pragma unroll
                for (int p = 0; p < 4; ++p) {
                    mma_tf32(acc[mt][2*p],   af[mt], bf[p].x, bf[p].y);
                    mma_tf32(acc[mt][2*p+1], af[mt], bf[p].z, bf[p].w);
                }
        }
    }

    const int bm = blockIdx.y * 128, bn = blockIdx.x * 128;
    #pragma unroll
    for (int mt = 0; mt < 2; ++mt) {
        #pragma unroll
        for (int j = 0; j < 8; ++j) {
            int m = bm + wm*32 + mt*16 + g;
            int n = bn + wn*64 + j*8 + t*2;
            *reinterpret_cast<float2*>(C + (size_t)m * Dq + n)       = make_float2(acc[mt][j][0], acc[mt][j][1]);
            *reinterpret_cast<float2*>(C + (size_t)(m + 8) * Dq + n) = make_float2(acc[mt][j][2], acc[mt][j][3]);
        }
    }
}

// ---------------------------------------------------------------------------
// Tensor-core causal flash attention.
// Block = 256 q-rows; 512 threads = 16 warps x m16; n=64 tiles.
// Output written directly in packed-A layout (staged through retired QA smem).
// Smem (u32): QA 0..16K | PA 16K..32K | KB 32K+s*4K | VB 40K+s*4K = 192KB.
// ---------------------------------------------------------------------------
extern __shared__ uint32_t sm_u[];
__global__ void __launch_bounds__(512, 1) attn_tc(const float* __restrict__ Qg,
                                                  const uint2* __restrict__ kp,
                                                  const uint2* __restrict__ vp,
                                                  uint32_t* __restrict__ ap)
{
    uint4* QA = reinterpret_cast<uint4*>(sm_u);              // 4096 u4 (64KB)
    uint4* PA = reinterpret_cast<uint4*>(sm_u + 16384);      // 4096 u4 (64KB)
    const uint32_t sbase = (uint32_t)__cvta_generic_to_shared(sm_u);

    const int tid  = threadIdx.x;
    const int lane = tid & 31, w = tid >> 5;                 // w: 0..15
    const int g = lane >> 2, t = lane & 3;
    const int qb = 7 - blockIdx.x;                           // heavy blocks first
    const int bh = blockIdx.y;
    const int b = bh >> 4, h = bh & 15;
    const size_t base = (size_t)b * Sq * Dq + (size_t)h * DKq;
    const int q0 = qb * 256;
    const float qsc = 0.125f * 1.44269504f;                  // fold log2e

    #pragma unroll
    for (int i = 0; i < 2; ++i) {
        int ta = tid + (i << 9);
        int kk = ta & 7, gg = (ta >> 3) & 7, sl = ta >> 6;
        int row = q0 + sl*16 + gg;
        const float* p0 = Qg + base + (size_t)row * Dq + kk*8;
        const float* p1 = p0 + 8*Dq;
        float4 a0 = *reinterpret_cast<const float4*>(p0);
        float4 a1 = *reinterpret_cast<const float4*>(p0 + 4);
        float4 b0 = *reinterpret_cast<const float4*>(p1);
        float4 b1 = *reinterpret_cast<const float4*>(p1 + 4);
        const float* fa0 = &a0.x; const float* fa1 = &a1.x;
        const float* fb0 = &b0.x; const float* fb1 = &b1.x;
        #pragma unroll
        for (int tt = 0; tt < 4; ++tt) {
            QA[sl*256 + gg*32 + 4*(kk ^ gg) + tt] =
                make_uint4(f2tf(fa0[tt]*qsc), f2tf(fb0[tt]*qsc),
                           f2tf(fa1[tt]*qsc), f2tf(fb1[tt]*qsc));
        }
    }

    auto prefetch = [&](int j, int s) {
        const uint4* kpt4 = reinterpret_cast<const uint4*>(kp) + ((size_t)bh * NTILES + j) * 1024;
        const uint4* vpt4 = reinterpret_cast<const uint4*>(vp) + ((size_t)bh * NTILES + j) * 1024;
        uint32_t sK = sbase + (32768 + s * 4096) * 4;
        uint32_t sV = sbase + (40960 + s * 4096) * 4;
        #pragma unroll
        for (int i = 0; i < 2; ++i)
            cp16(sK + (tid + (i << 9)) * 16, kpt4 + tid + (i << 9));
        #pragma unroll
        for (int i = 0; i < 2; ++i)
            cp16(sV + (tid + (i << 9)) * 16, vpt4 + tid + (i << 9));
    };

    const int row_hi = q0 + w*16 + 15;
    float mst0 = LNEG, mst1 = LNEG, lst0 = 0.f, lst1 = 0.f;
    float Od[8][4];
    #pragma unroll
    for (int n8 = 0; n8 < 8; ++n8)
        #pragma unroll
        for (int e = 0; e < 4; ++e) Od[n8][e] = 0.f;

    const int jmax = 4*qb + 3;
    prefetch(0, 0);
    asm volatile("cp.async.commit_group;");

    for (int j = 0; j <= jmax; ++j) {
        const int s = j & 1;
        const int key0 = j << 6;
        if (j + 1 <= jmax) prefetch(j + 1, s ^ 1);
        asm volatile("cp.async.commit_group;");
        asm volatile("cp.async.wait_group 1;");
        __syncthreads();

        if (key0 <= row_hi) {
            const uint2* KBs = reinterpret_cast<const uint2*>(sm_u + 32768 + s * 4096);
            const uint2* VBs = reinterpret_cast<const uint2*>(sm_u + 40960 + s * 4096);

            float acc[8][4];
            #pragma unroll
            for (int n8 = 0; n8 < 8; ++n8)
                #pragma unroll
                for (int e = 0; e < 4; ++e) acc[n8][e] = 0.f;

            #pragma unroll
            for (int kk = 0; kk < 8; ++kk) {
                uint4 aq = QA[w*256 + g*32 + 4*(kk ^ g) + t];
                #pragma unroll
                for (int n8 = 0; n8 < 8; ++n8) {
                    uint2 kb = KBs[(8*n8 + g)*32 + 4*(kk ^ g) + (t ^ (n8 & 3))];
                    mma_tf32(acc[n8], aq, kb.x, kb.y);
                }
            }
            if (key0 + 63 > q0 + w*16) {
                int r0 = q0 + w*16 + g, r1 = r0 + 8;
                #pragma unroll
                for (int n8 = 0; n8 < 8; ++n8) {
                    int c0 = key0 + 8*n8 + 2*t, c1 = c0 + 1;
                    if (c0 > r0) acc[n8][0] = LNEG;
                    if (c1 > r0) acc[n8][1] = LNEG;
                    if (c0 > r1) acc[n8][2] = LNEG;
                    if (c1 > r1) acc[n8][3] = LNEG;
                }
            }
            float t0 = LNEG, t1 = LNEG;
            #pragma unroll
            for (int n8 = 0; n8 < 8; ++n8) {
                t0 = fmaxf(t0, fmaxf(acc[n8][0], acc[n8][1]));
                t1 = fmaxf(t1, fmaxf(acc[n8][2], acc[n8][3]));
            }
            t0 = fmaxf(t0, __shfl_xor_sync(0xffffffffu, t0, 1));
            t0 = fmaxf(t0, __shfl_xor_sync(0xffffffffu, t0, 2));
            t1 = fmaxf(t1, __shfl_xor_sync(0xffffffffu, t1, 1));
            t1 = fmaxf(t1, __shfl_xor_sync(0xffffffffu, t1, 2));
            float m0n = fmaxf(mst0, t0), m1n = fmaxf(mst1, t1);
            float c0 = ex2(mst0 - m0n), c1 = ex2(mst1 - m1n);
            float s0 = 0.f, s1 = 0.f;

            int d0 = 2*t, d1 = 2*t + 1;
            int tw0 = d0 & 3, sl0 = (d0 >> 2) << 1;
            int tw1 = d1 & 3, sl1 = (d1 >> 2) << 1;
            #pragma unroll
            for (int n8 = 0; n8 < 8; ++n8) {
                float p00 = ex2(acc[n8][0] - m0n);
                float p01 = ex2(acc[n8][1] - m0n);
                float p10 = ex2(acc[n8][2] - m1n);
                float p11 = ex2(acc[n8][3] - m1n);
                s0 += p00 + p01;
                s1 += p10 + p11;
                uint32_t* pw = reinterpret_cast<uint32_t*>(&PA[w*256 + g*32 + 4*(n8 ^ g)]);
                pw[tw0*4 + sl0]     = f2tf(p00);
                pw[tw0*4 + sl0 + 1] = f2tf(p10);
                pw[tw1*4 + sl1]     = f2tf(p01);
                pw[tw1*4 + sl1 + 1] = f2tf(p11);
            }
            lst0 = lst0 * c0 + s0;
            lst1 = lst1 * c1 + s1;
            mst0 = m0n; mst1 = m1n;
            #pragma unroll
            for (int n8 = 0; n8 < 8; ++n8) {
                Od[n8][0] *= c0; Od[n8][1] *= c0;
                Od[n8][2] *= c1; Od[n8][3] *= c1;
            }
            __syncwarp();

            #pragma unroll
            for (int kk = 0; kk < 8; ++kk) {
                uint4 pa = PA[w*256 + g*32 + 4*(kk ^ g) + t];
                #pragma unroll
                for (int n8 = 0; n8 < 8; ++n8) {
                    uint2 vb = VBs[(8*n8 + g)*32 + 4*(kk ^ g) + (t ^ (n8 & 3))];
                    mma_tf32(Od[n8], pa, vb.x, vb.y);
                }
            }
        }
        __syncthreads();
    }

    // ---- epilogue: normalize, stage packed-A layout in QA smem, copy out ----
    lst0 += __shfl_xor_sync(0xffffffffu, lst0, 1);
    lst0 += __shfl_xor_sync(0xffffffffu, lst0, 2);
    lst1 += __shfl_xor_sync(0xffffffffu, lst1, 1);
    lst1 += __shfl_xor_sync(0xffffffffu, lst1, 2);
    float i0 = 1.f / lst0, i1 = 1.f / lst1;

    #pragma unroll
    for (int n8 = 0; n8 < 8; ++n8)
        #pragma unroll
        for (int e = 0; e < 4; ++e) {
            float val = Od[n8][e] * ((e >> 1) ? i1 : i0);
            int row_loc = w*16 + g + ((e >> 1) << 3);     // 0..255
            int col_loc = 8*n8 + 2*t + (e & 1);           // 0..63
            int rh = row_loc >> 7, r = row_loc & 127;
            int chh = col_loc >> 5, c = col_loc & 31;
            int mt = r >> 4, rr = r & 15;
            int ks = c >> 3, hi = (c >> 2) & 1, jw = c & 3;
            int idx = ((mt*4 + ks)*32 + ((((rr & 7) << 2) | jw) ^ (ks << 1)))*4 + (rr >> 3) + 2*hi;
            sm_u[(rh*2 + chh)*4096 + idx] = f2tf(val);
        }
    __syncthreads();

    #pragma unroll
    for (int qd = 0; qd < 4; ++qd) {
        int rh = qd >> 1, chh = qd & 1;
        int rb = b*16 + qb*2 + rh;
        int ch = h*2 + chh;
        uint4* dst = reinterpret_cast<uint4*>(ap) + ((size_t)rb * NCH + ch) * 1024;
        const uint4* src = reinterpret_cast<const uint4*>(sm_u) + qd * 1024;
        #pragma unroll
        for (int i = 0; i < 2; ++i)
            dst[tid + (i << 9)] = src[tid + (i << 9)];
    }
}

// ---------------------------------------------------------------------------
extern "C" void kernel_launch(void* const* d_in, const int* in_sizes, int n_in,
                              void* d_out, int out_size)
{
    const float* x  = (const float*)d_in[0];
    const float* wq = (const float*)d_in[1];
    const float* wk = (const float*)d_in[2];
    const float* wv = (const float*)d_in[3];
    const float* wo = (const float*)d_in[4];
    float* out = (float*)d_out;

    float *q;
    uint4 *xp, *ap, *pwq, *pwk, *pwv, *pwo;
    uint2 *kpp, *vpp;
    cudaGetSymbolAddress((void**)&q,   g_q);
    cudaGetSymbolAddress((void**)&kpp, g_kp);
    cudaGetSymbolAddress((void**)&vpp, g_vp);
    cudaGetSymbolAddress((void**)&xp,  g_xp);
    cudaGetSymbolAddress((void**)&ap,  g_ap);
    cudaGetSymbolAddress((void**)&pwq, g_wq);
    cudaGetSymbolAddress((void**)&pwk, g_wk);
    cudaGetSymbolAddress((void**)&pwv, g_wv);
    cudaGetSymbolAddress((void**)&pwo, g_wo);

    pack_a<<<dim3(Mrows/128, NCH), 256>>>(x, (uint32_t*)xp);
    pack_w<<<dim3(8, NCH, 4), 256>>>(wq, wk, wv, wo,
                                     (uint32_t*)pwq, (uint32_t*)pwk,
                                     (uint32_t*)pwv, (uint32_t*)pwo);

    int smem_gemm = 98304;
    cudaFuncSetAttribute(gemm_qkv,    cudaFuncAttributeMaxDynamicSharedMemorySize, smem_gemm);
    cudaFuncSetAttribute(gemm_packed, cudaFuncAttributeMaxDynamicSharedMemorySize, smem_gemm);

    gemm_qkv<<<dim3(8, 64, 3), 256, smem_gemm>>>(xp, pwq, pwk, pwv, q,
                                                 (uint32_t*)kpp, (uint32_t*)vpp);

    int smem_attn = 196608;   // 192KB
    cudaFuncSetAttribute(attn_tc, cudaFuncAttributeMaxDynamicSharedMemorySize, smem_attn);
    attn_tc<<<dim3(8, 64), 512, smem_attn>>>(q, kpp, vpp, (uint32_t*)ap);

    gemm_packed<<<dim3(8, 64), 256, smem_gemm>>>(ap, pwo, out);
}

// round 11
// speedup vs baseline: 7.5456x; 1.0350x over previous
#include <cuda_runtime.h>
#include <cstdint>
#include <cstddef>

#define Bq 4
#define Sq 2048
#define Dq 1024
#define Hq 16
#define DKq 64
#define Mrows (Bq*Sq)
#define NTILES 32          // key tiles per (b,h)
#define NCH 32             // K chunks per GEMM (K=1024 / 32)
#define LNEG -1e30f

// Scratch (allocation-free rule: __device__ globals)
__device__ float g_q[Mrows*Dq];
__device__ uint4 g_kp[(size_t)64*NTILES*1024];     // packed K fragments (paired n8)
__device__ uint4 g_vp[(size_t)64*NTILES*1024];     // packed V fragments (paired n8)
__device__ uint4 g_xp[(size_t)Mrows*Dq/4];          // packed x   (A layout)
__device__ uint4 g_ap[(size_t)Mrows*Dq/4];          // packed attn out (A layout)
__device__ uint4 g_wq[(size_t)Dq*Dq/4];             // packed weights (B layout)
__device__ uint4 g_wk[(size_t)Dq*Dq/4];
__device__ uint4 g_wv[(size_t)Dq*Dq/4];
__device__ uint4 g_wo[(size_t)Dq*Dq/4];

__device__ __forceinline__ uint32_t f2tf(float f) {
    uint32_t u;
    asm("cvt.rna.tf32.f32 %0, %1;" : "=r"(u) : "f"(f));
    return u;
}
__device__ __forceinline__ float ex2(float x) {
    float r;
    asm("ex2.approx.f32 %0, %1;" : "=f"(r) : "f"(x));
    return r;
}
__device__ __forceinline__ void mma_tf32(float* c, uint4 a, uint32_t b0, uint32_t b1) {
    asm volatile("mma.sync.aligned.m16n8k8.row.col.f32.tf32.tf32.f32 "
        "{%0,%1,%2,%3}, {%4,%5,%6,%7}, {%8,%9}, {%0,%1,%2,%3};"
        : "+f"(c[0]), "+f"(c[1]), "+f"(c[2]), "+f"(c[3])
        : "r"(a.x), "r"(a.y), "r"(a.z), "r"(a.w), "r"(b0), "r"(b1));
}
__device__ __forceinline__ void cp16(uint32_t sa, const void* g) {
    asm volatile("cp.async.cg.shared.global [%0], [%1], 16;" :: "r"(sa), "l"(g));
}

// ---------------------------------------------------------------------------
// Pack a float matrix [R x 1024] into A-layout fragment tiles (TF32).
// ---------------------------------------------------------------------------
__global__ void __launch_bounds__(256) pack_a(const float* __restrict__ A,
                                              uint32_t* __restrict__ out)
{
    const int rb = blockIdx.x, ch = blockIdx.y, tid = threadIdx.x;
    const int rbase = tid >> 3, kc = (tid & 7) << 2;
    const int ks = (tid & 7) >> 1, hi = tid & 1;
    uint32_t* ot = out + ((size_t)rb * NCH + ch) * 4096;
    const float* Ab = A + ((size_t)rb * 128) * Dq + ch * 32;
    #pragma unroll
    for (int i = 0; i < 4; ++i) {
        int r = rbase + 32*i;
        float4 f4 = *reinterpret_cast<const float4*>(Ab + (size_t)r * Dq + kc);
        const float* f = &f4.x;
        int mt = r >> 4, rr = r & 15;
        int w = (rr >> 3) + (hi << 1);
        int base = (mt*4 + ks) * 32;
        int l0 = (rr & 7) << 2;
        #pragma unroll
        for (int j = 0; j < 4; ++j)
            ot[(base + ((l0 + j) ^ (ks << 1))) * 4 + w] = f2tf(f[j]);
    }
}

// ---------------------------------------------------------------------------
// Pack the 4 weight matrices into B-layout fragment tiles.
// ---------------------------------------------------------------------------
__global__ void __launch_bounds__(256) pack_w(const float* __restrict__ w0,
                                              const float* __restrict__ w1,
                                              const float* __restrict__ w2,
                                              const float* __restrict__ w3,
                                              uint32_t* __restrict__ o0,
                                              uint32_t* __restrict__ o1,
                                              uint32_t* __restrict__ o2,
                                              uint32_t* __restrict__ o3)
{
    const float* W = (blockIdx.z == 0) ? w0 : (blockIdx.z == 1) ? w1
                    : (blockIdx.z == 2) ? w2 : w3;
    uint32_t* O = (blockIdx.z == 0) ? o0 : (blockIdx.z == 1) ? o1
                 : (blockIdx.z == 2) ? o2 : o3;
    const int nb = blockIdx.x, ch = blockIdx.y, tid = threadIdx.x;
    const int rbase = tid >> 3, kc = (tid & 7) << 2;
    const int ks = (tid & 7) >> 1, hi = tid & 1;
    uint32_t* ot = O + ((size_t)nb * NCH + ch) * 4096;
    const float* Wb = W + ((size_t)nb * 128) * Dq + ch * 32;
    #pragma unroll
    for (int i = 0; i < 4; ++i) {
        int n = rbase + 32*i;
        float4 f4 = *reinterpret_cast<const float4*>(Wb + (size_t)n * Dq + kc);
        const float* f = &f4.x;
        int nt = n >> 3, gg = n & 7;
        int w = ((nt & 1) << 1) + hi;
        int base = ((nt >> 1)*4 + ks) * 32;
        int l0 = gg << 2;
        #pragma unroll
        for (int j = 0; j < 4; ++j)
            ot[(base + ((l0 + j) ^ (ks << 1))) * 4 + w] = f2tf(f[j]);
    }
}

// ---------------------------------------------------------------------------
// Fused QKV TF32 GEMM on pre-packed operands. grid (8, 64, 3).
// z=0: C=x@Wq^T -> float g_q.  z=1: x@Wk^T -> paired kp.  z=2: x@Wv^T -> vp.
// K/V epilogues stage the PAIRED uint4 fragment layout:
//   u32 idx = ((q*8+g)*32 + 4*(kk^g) + tt)*4 + half*2 + hi
// where for K: g=key&7, q=(key>>3)>>1, half=(key>>3)&1, kk=dk>>3, tt=(dk&7)&3,
// hi=(dk&7)>>2;  for V roles of key/dk swap.
// ---------------------------------------------------------------------------
extern __shared__ uint32_t gsm[];
__global__ void __launch_bounds__(256, 2) gemm_qkv(const uint4* __restrict__ Ap,
                                                   const uint4* __restrict__ Bq_,
                                                   const uint4* __restrict__ Bk_,
                                                   const uint4* __restrict__ Bv_,
                                                   float* __restrict__ Cq,
                                                   uint32_t* __restrict__ kp32,
                                                   uint32_t* __restrict__ vp32)
{
    const int tid = threadIdx.x;
    const int lane = tid & 31, wid = tid >> 5;
    const int wm = wid >> 1, wn = wid & 1;
    const int g = lane >> 2, t = lane & 3;
    const int z = blockIdx.z;
    const uint4* Bp = (z == 0) ? Bq_ : (z == 1) ? Bk_ : Bv_;
    const size_t tA0 = (size_t)blockIdx.y * NCH;
    const size_t tB0 = (size_t)blockIdx.x * NCH;
    const uint32_t sbase = (uint32_t)__cvta_generic_to_shared(gsm);

    float acc[2][8][4];
    #pragma unroll
    for (int mt = 0; mt < 2; ++mt)
        #pragma unroll
        for (int j = 0; j < 8; ++j)
            #pragma unroll
            for (int e = 0; e < 4; ++e) acc[mt][j][e] = 0.f;

    auto prefetch = [&](int ch, int s) {
        const uint4* ga = Ap + (tA0 + ch) * 1024 + tid;
        const uint4* gb = Bp + (tB0 + ch) * 1024 + tid;
        uint32_t sA = sbase + s * 32768;
        uint32_t sB = sA + 16384;
        #pragma unroll
        for (int i = 0; i < 4; ++i)
            cp16(sA + (tid + (i << 8)) * 16, ga + (i << 8));
        #pragma unroll
        for (int i = 0; i < 4; ++i)
            cp16(sB + (tid + (i << 8)) * 16, gb + (i << 8));
    };

    prefetch(0, 0);
    asm volatile("cp.async.commit_group;");
    prefetch(1, 1);
    asm volatile("cp.async.commit_group;");

    for (int ch = 0; ch < NCH; ++ch) {
        const int s = ch % 3;
        asm volatile("cp.async.wait_group 1;");
        __syncthreads();
        if (ch + 2 < NCH) prefetch(ch + 2, (ch + 2) % 3);
        asm volatile("cp.async.commit_group;");

        const uint32_t* As = gsm + s * 8192;
        const uint32_t* Bs = As + 4096;
        #pragma unroll
        for (int ks = 0; ks < 4; ++ks) {
            uint4 af[2], bf[4];
            const int sl = lane ^ (ks << 1);
            #pragma unroll
            for (int mt = 0; mt < 2; ++mt)
                af[mt] = *reinterpret_cast<const uint4*>(
                    &As[(((wm*2 + mt)*4 + ks)*32 + sl) * 4]);
            #pragma unroll
            for (int p = 0; p < 4; ++p)
                bf[p] = *reinterpret_cast<const uint4*>(
                    &Bs[(((wn*4 + p)*4 + ks)*32 + sl) * 4]);
            #pragma unroll
            for (int mt = 0; mt < 2; ++mt)
                #pragma unroll
                for (int p = 0; p < 4; ++p) {
                    mma_tf32(acc[mt][2*p],   af[mt], bf[p].x, bf[p].y);
                    mma_tf32(acc[mt][2*p+1], af[mt], bf[p].z, bf[p].w);
                }
        }
    }

    const int bm = blockIdx.y * 128, bn = blockIdx.x * 128;

    if (z == 0) {
        #pragma unroll
        for (int mt = 0; mt < 2; ++mt)
            #pragma unroll
            for (int j = 0; j < 8; ++j) {
                int m = bm + wm*32 + mt*16 + g;
                int n = bn + wn*64 + j*8 + t*2;
                *reinterpret_cast<float2*>(Cq + (size_t)m * Dq + n)       = make_float2(acc[mt][j][0], acc[mt][j][1]);
                *reinterpret_cast<float2*>(Cq + (size_t)(m + 8) * Dq + n) = make_float2(acc[mt][j][2], acc[mt][j][3]);
            }
        return;
    }

    // K/V: stage paired-fragment layout into smem, then coalesced copy
    asm volatile("cp.async.wait_group 0;");
    __syncthreads();          // pipeline dead; gsm reusable

    #pragma unroll
    for (int mt = 0; mt < 2; ++mt)
        #pragma unroll
        for (int j = 0; j < 8; ++j)
            #pragma unroll
            for (int e = 0; e < 4; ++e) {
                int rloc = wm*32 + mt*16 + g + ((e >> 1) << 3);   // 0..127
                int nloc = wn*64 + j*8 + 2*t + (e & 1);           // 0..127
                int rh = rloc >> 6, ch2 = nloc >> 6;
                int keyl = rloc & 63, dkl = nloc & 63;
                int idx;
                if (z == 1) {
                    int gq = keyl & 7, n8k = keyl >> 3;
                    int qk = n8k >> 1, half = n8k & 1;
                    int kk2 = dkl >> 3, dc = dkl & 7;
                    idx = ((qk*8 + gq)*32 + 4*(kk2 ^ gq) + (dc & 3))*4 + half*2 + (dc >> 2);
                } else {
                    int gq = dkl & 7, n8v = dkl >> 3;
                    int qv = n8v >> 1, half = n8v & 1;
                    int kk3 = keyl >> 3, kc2 = keyl & 7;
                    idx = ((qv*8 + gq)*32 + 4*(kk3 ^ gq) + (kc2 & 3))*4 + half*2 + (kc2 >> 2);
                }
                gsm[(rh*2 + ch2)*4096 + idx] = f2tf(acc[mt][j][e]);
            }
    __syncthreads();

    uint32_t* dstb = (z == 1) ? kp32 : vp32;
    const int b = bm >> 11, jt0 = (bm & 2047) >> 6, h0 = bn >> 6;
    #pragma unroll
    for (int qd = 0; qd < 4; ++qd) {
        int rh = qd >> 1, ch2 = qd & 1;
        int bh = b*16 + h0 + ch2;
        int jt = jt0 + rh;
        uint4* dst = reinterpret_cast<uint4*>(dstb) + ((size_t)bh*NTILES + jt) * 1024;
        const uint4* src = reinterpret_cast<const uint4*>(gsm) + qd * 1024;
        #pragma unroll
        for (int i = 0; i < 4; ++i)
            dst[tid + (i << 8)] = src[tid + (i << 8)];
    }
}

// ---------------------------------------------------------------------------
// TF32 GEMM on pre-packed operands (final O-projection), float epilogue.
// ---------------------------------------------------------------------------
__global__ void __launch_bounds__(256, 2) gemm_packed(const uint4* __restrict__ Ap,
                                                      const uint4* __restrict__ Bp,
                                                      float* __restrict__ C)
{
    const int tid = threadIdx.x;
    const int lane = tid & 31, wid = tid >> 5;
    const int wm = wid >> 1, wn = wid & 1;
    const int g = lane >> 2, t = lane & 3;
    const size_t tA0 = (size_t)blockIdx.y * NCH;
    const size_t tB0 = (size_t)blockIdx.x * NCH;
    const uint32_t sbase = (uint32_t)__cvta_generic_to_shared(gsm);

    float acc[2][8][4];
    #pragma unroll
    for (int mt = 0; mt < 2; ++mt)
        #pragma unroll
        for (int j = 0; j < 8; ++j)
            #pragma unroll
            for (int e = 0; e < 4; ++e) acc[mt][j][e] = 0.f;

    auto prefetch = [&](int ch, int s) {
        const uint4* ga = Ap + (tA0 + ch) * 1024 + tid;
        const uint4* gb = Bp + (tB0 + ch) * 1024 + tid;
        uint32_t sA = sbase + s * 32768;
        uint32_t sB = sA + 16384;
        #pragma unroll
        for (int i = 0; i < 4; ++i)
            cp16(sA + (tid + (i << 8)) * 16, ga + (i << 8));
        #pragma unroll
        for (int i = 0; i < 4; ++i)
            cp16(sB + (tid + (i << 8)) * 16, gb + (i << 8));
    };

    prefetch(0, 0);
    asm volatile("cp.async.commit_group;");
    prefetch(1, 1);
    asm volatile("cp.async.commit_group;");

    for (int ch = 0; ch < NCH; ++ch) {
        const int s = ch % 3;
        asm volatile("cp.async.wait_group 1;");
        __syncthreads();
        if (ch + 2 < NCH) prefetch(ch + 2, (ch + 2) % 3);
        asm volatile("cp.async.commit_group;");

        const uint32_t* As = gsm + s * 8192;
        const uint32_t* Bs = As + 4096;
        #pragma unroll
        for (int ks = 0; ks < 4; ++ks) {
            uint4 af[2], bf[4];
            const int sl = lane ^ (ks << 1);
            #pragma unroll
            for (int mt = 0; mt < 2; ++mt)
                af[mt] = *reinterpret_cast<const uint4*>(
                    &As[(((wm*2 + mt)*4 + ks)*32 + sl) * 4]);
            #pragma unroll
            for (int p = 0; p < 4; ++p)
                bf[p] = *reinterpret_cast<const uint4*>(
                    &Bs[(((wn*4 + p)*4 + ks)*32 + sl) * 4]);
            #pragma unroll
            for (int mt = 0; mt < 2; ++mt)
                #pragma unroll
                for (int p = 0; p < 4; ++p) {
                    mma_tf32(acc[mt][2*p],   af[mt], bf[p].x, bf[p].y);
                    mma_tf32(acc[mt][2*p+1], af[mt], bf[p].z, bf[p].w);
                }
        }
    }

    const int bm = blockIdx.y * 128, bn = blockIdx.x * 128;
    #pragma unroll
    for (int mt = 0; mt < 2; ++mt) {
        #pragma unroll
        for (int j = 0; j < 8; ++j) {
            int m = bm + wm*32 + mt*16 + g;
            int n = bn + wn*64 + j*8 + t*2;
            *reinterpret_cast<float2*>(C + (size_t)m * Dq + n)       = make_float2(acc[mt][j][0], acc[mt][j][1]);
            *reinterpret_cast<float2*>(C + (size_t)(m + 8) * Dq + n) = make_float2(acc[mt][j][2], acc[mt][j][3]);
        }
    }
}

// ---------------------------------------------------------------------------
// Tensor-core causal flash attention.
// Block = 256 q-rows; 512 threads = 16 warps x m16; n=64 tiles.
// Paired B fragments: one LDS.128 feeds two mmas (n8=2q, 2q+1).
// Warp-vote skip of the Od rescale when max unchanged (bit-identical).
// Smem (u32): QA 0..16K | PA 16K..32K | KB 32K+s*4K | VB 40K+s*4K = 192KB.
// ---------------------------------------------------------------------------
extern __shared__ uint32_t sm_u[];
__global__ void __launch_bounds__(512, 1) attn_tc(const float* __restrict__ Qg,
                                                  const uint4* __restrict__ kp,
                                                  const uint4* __restrict__ vp,
                                                  uint32_t* __restrict__ ap)
{
    uint4* QA = reinterpret_cast<uint4*>(sm_u);              // 4096 u4 (64KB)
    uint4* PA = reinterpret_cast<uint4*>(sm_u + 16384);      // 4096 u4 (64KB)
    const uint32_t sbase = (uint32_t)__cvta_generic_to_shared(sm_u);

    const int tid  = threadIdx.x;
    const int lane = tid & 31, w = tid >> 5;                 // w: 0..15
    const int g = lane >> 2, t = lane & 3;
    const int qb = 7 - blockIdx.x;                           // heavy blocks first
    const int bh = blockIdx.y;
    const int b = bh >> 4, h = bh & 15;
    const size_t base = (size_t)b * Sq * Dq + (size_t)h * DKq;
    const int q0 = qb * 256;
    const float qsc = 0.125f * 1.44269504f;                  // fold log2e

    #pragma unroll
    for (int i = 0; i < 2; ++i) {
        int ta = tid + (i << 9);
        int kk = ta & 7, gg = (ta >> 3) & 7, sl = ta >> 6;
        int row = q0 + sl*16 + gg;
        const float* p0 = Qg + base + (size_t)row * Dq + kk*8;
        const float* p1 = p0 + 8*Dq;
        float4 a0 = *reinterpret_cast<const float4*>(p0);
        float4 a1 = *reinterpret_cast<const float4*>(p0 + 4);
        float4 b0 = *reinterpret_cast<const float4*>(p1);
        float4 b1 = *reinterpret_cast<const float4*>(p1 + 4);
        const float* fa0 = &a0.x; const float* fa1 = &a1.x;
        const float* fb0 = &b0.x; const float* fb1 = &b1.x;
        #pragma unroll
        for (int tt = 0; tt < 4; ++tt) {
            QA[sl*256 + gg*32 + 4*(kk ^ gg) + tt] =
                make_uint4(f2tf(fa0[tt]*qsc), f2tf(fb0[tt]*qsc),
                           f2tf(fa1[tt]*qsc), f2tf(fb1[tt]*qsc));
        }
    }

    auto prefetch = [&](int j, int s) {
        const uint4* kpt4 = kp + ((size_t)bh * NTILES + j) * 1024;
        const uint4* vpt4 = vp + ((size_t)bh * NTILES + j) * 1024;
        uint32_t sK = sbase + (32768 + s * 4096) * 4;
        uint32_t sV = sbase + (40960 + s * 4096) * 4;
        #pragma unroll
        for (int i = 0; i < 2; ++i)
            cp16(sK + (tid + (i << 9)) * 16, kpt4 + tid + (i << 9));
        #pragma unroll
        for (int i = 0; i < 2; ++i)
            cp16(sV + (tid + (i << 9)) * 16, vpt4 + tid + (i << 9));
    };

    const int row_hi = q0 + w*16 + 15;
    float mst0 = LNEG, mst1 = LNEG, lst0 = 0.f, lst1 = 0.f;
    float Od[8][4];
    #pragma unroll
    for (int n8 = 0; n8 < 8; ++n8)
        #pragma unroll
        for (int e = 0; e < 4; ++e) Od[n8][e] = 0.f;

    const int jmax = 4*qb + 3;
    prefetch(0, 0);
    asm volatile("cp.async.commit_group;");

    for (int j = 0; j <= jmax; ++j) {
        const int s = j & 1;
        const int key0 = j << 6;
        if (j + 1 <= jmax) prefetch(j + 1, s ^ 1);
        asm volatile("cp.async.commit_group;");
        asm volatile("cp.async.wait_group 1;");
        __syncthreads();

        if (key0 <= row_hi) {
            const uint4* KB4 = reinterpret_cast<const uint4*>(sm_u + 32768 + s * 4096);
            const uint4* VB4 = reinterpret_cast<const uint4*>(sm_u + 40960 + s * 4096);

            float acc[8][4];
            #pragma unroll
            for (int n8 = 0; n8 < 8; ++n8)
                #pragma unroll
                for (int e = 0; e < 4; ++e) acc[n8][e] = 0.f;

            // ---- QK^T: one LDS.128 per n8-pair ----
            #pragma unroll
            for (int kk = 0; kk < 8; ++kk) {
                uint4 aq = QA[w*256 + g*32 + 4*(kk ^ g) + t];
                #pragma unroll
                for (int qp = 0; qp < 4; ++qp) {
                    uint4 kb = KB4[(qp*8 + g)*32 + 4*(kk ^ g) + t];
                    mma_tf32(acc[2*qp],   aq, kb.x, kb.y);
                    mma_tf32(acc[2*qp+1], aq, kb.z, kb.w);
                }
            }
            if (key0 + 63 > q0 + w*16) {
                int r0 = q0 + w*16 + g, r1 = r0 + 8;
                #pragma unroll
                for (int n8 = 0; n8 < 8; ++n8) {
                    int c0 = key0 + 8*n8 + 2*t, c1 = c0 + 1;
                    if (c0 > r0) acc[n8][0] = LNEG;
                    if (c1 > r0) acc[n8][1] = LNEG;
                    if (c0 > r1) acc[n8][2] = LNEG;
                    if (c1 > r1) acc[n8][3] = LNEG;
                }
            }
            float t0 = LNEG, t1 = LNEG;
            #pragma unroll
            for (int n8 = 0; n8 < 8; ++n8) {
                t0 = fmaxf(t0, fmaxf(acc[n8][0], acc[n8][1]));
                t1 = fmaxf(t1, fmaxf(acc[n8][2], acc[n8][3]));
            }
            t0 = fmaxf(t0, __shfl_xor_sync(0xffffffffu, t0, 1));
            t0 = fmaxf(t0, __shfl_xor_sync(0xffffffffu, t0, 2));
            t1 = fmaxf(t1, __shfl_xor_sync(0xffffffffu, t1, 1));
            t1 = fmaxf(t1, __shfl_xor_sync(0xffffffffu, t1, 2));
            float m0n = fmaxf(mst0, t0), m1n = fmaxf(mst1, t1);
            bool same = (m0n == mst0) && (m1n == mst1);
            bool allsame = __all_sync(0xffffffffu, same);
            float c0 = ex2(mst0 - m0n), c1 = ex2(mst1 - m1n);
            float s0 = 0.f, s1 = 0.f;

            int d0 = 2*t, d1 = 2*t + 1;
            int tw0 = d0 & 3, sl0 = (d0 >> 2) << 1;
            int tw1 = d1 & 3, sl1 = (d1 >> 2) << 1;
            #pragma unroll
            for (int n8 = 0; n8 < 8; ++n8) {
                float p00 = ex2(acc[n8][0] - m0n);
                float p01 = ex2(acc[n8][1] - m0n);
                float p10 = ex2(acc[n8][2] - m1n);
                float p11 = ex2(acc[n8][3] - m1n);
                s0 += p00 + p01;
                s1 += p10 + p11;
                uint32_t* pw = reinterpret_cast<uint32_t*>(&PA[w*256 + g*32 + 4*(n8 ^ g)]);
                pw[tw0*4 + sl0]     = f2tf(p00);
                pw[tw0*4 + sl0 + 1] = f2tf(p10);
                pw[tw1*4 + sl1]     = f2tf(p01);
                pw[tw1*4 + sl1 + 1] = f2tf(p11);
            }
            lst0 = lst0 * c0 + s0;       // c==1 exactly when max unchanged
            lst1 = lst1 * c1 + s1;
            mst0 = m0n; mst1 = m1n;
            if (!allsame) {
                #pragma unroll
                for (int n8 = 0; n8 < 8; ++n8) {
                    Od[n8][0] *= c0; Od[n8][1] *= c0;
                    Od[n8][2] *= c1; Od[n8][3] *= c1;
                }
            }
            __syncwarp();

            // ---- P @ V: one LDS.128 per n8-pair ----
            #pragma unroll
            for (int kk = 0; kk < 8; ++kk) {
                uint4 pa = PA[w*256 + g*32 + 4*(kk ^ g) + t];
                #pragma unroll
                for (int qp = 0; qp < 4; ++qp) {
                    uint4 vb = VB4[(qp*8 + g)*32 + 4*(kk ^ g) + t];
                    mma_tf32(Od[2*qp],   pa, vb.x, vb.y);
                    mma_tf32(Od[2*qp+1], pa, vb.z, vb.w);
                }
            }
        }
        __syncthreads();
    }

    // ---- epilogue: normalize, stage packed-A layout in QA smem, copy out ----
    lst0 += __shfl_xor_sync(0xffffffffu, lst0, 1);
    lst0 += __shfl_xor_sync(0xffffffffu, lst0, 2);
    lst1 += __shfl_xor_sync(0xffffffffu, lst1, 1);
    lst1 += __shfl_xor_sync(0xffffffffu, lst1, 2);
    float i0 = 1.f / lst0, i1 = 1.f / lst1;

    #pragma unroll
    for (int n8 = 0; n8 < 8; ++n8)
        #pragma unroll
        for (int e = 0; e < 4; ++e) {
            float val = Od[n8][e] * ((e >> 1) ? i1 : i0);
            int row_loc = w*16 + g + ((e >> 1) << 3);     // 0..255
            int col_loc = 8*n8 + 2*t + (e & 1);           // 0..63
            int rh = row_loc >> 7, r = row_loc & 127;
            int chh = col_loc >> 5, c = col_loc & 31;
            int mt = r >> 4, rr = r & 15;
            int ks = c >> 3, hi = (c >> 2) & 1, jw = c & 3;
            int idx = ((mt*4 + ks)*32 + ((((rr & 7) << 2) | jw) ^ (ks << 1)))*4 + (rr >> 3) + 2*hi;
            sm_u[(rh*2 + chh)*4096 + idx] = f2tf(val);
        }
    __syncthreads();

    #pragma unroll
    for (int qd = 0; qd < 4; ++qd) {
        int rh = qd >> 1, chh = qd & 1;
        int rb = b*16 + qb*2 + rh;
        int ch = h*2 + chh;
        uint4* dst = reinterpret_cast<uint4*>(ap) + ((size_t)rb * NCH + ch) * 1024;
        const uint4* src = reinterpret_cast<const uint4*>(sm_u) + qd * 1024;
        #pragma unroll
        for (int i = 0; i < 2; ++i)
            dst[tid + (i << 9)] = src[tid + (i << 9)];
    }
}

// ---------------------------------------------------------------------------
extern "C" void kernel_launch(void* const* d_in, const int* in_sizes, int n_in,
                              void* d_out, int out_size)
{
    const float* x  = (const float*)d_in[0];
    const float* wq = (const float*)d_in[1];
    const float* wk = (const float*)d_in[2];
    const float* wv = (const float*)d_in[3];
    const float* wo = (const float*)d_in[4];
    float* out = (float*)d_out;

    float *q;
    uint4 *xp, *ap, *pwq, *pwk, *pwv, *pwo, *kpp, *vpp;
    cudaGetSymbolAddress((void**)&q,   g_q);
    cudaGetSymbolAddress((void**)&kpp, g_kp);
    cudaGetSymbolAddress((void**)&vpp, g_vp);
    cudaGetSymbolAddress((void**)&xp,  g_xp);
    cudaGetSymbolAddress((void**)&ap,  g_ap);
    cudaGetSymbolAddress((void**)&pwq, g_wq);
    cudaGetSymbolAddress((void**)&pwk, g_wk);
    cudaGetSymbolAddress((void**)&pwv, g_wv);
    cudaGetSymbolAddress((void**)&pwo, g_wo);

    pack_a<<<dim3(Mrows/128, NCH), 256>>>(x, (uint32_t*)xp);
    pack_w<<<dim3(8, NCH, 4), 256>>>(wq, wk, wv, wo,
                                     (uint32_t*)pwq, (uint32_t*)pwk,
                                     (uint32_t*)pwv, (uint32_t*)pwo);

    int smem_gemm = 98304;
    cudaFuncSetAttribute(gemm_qkv,    cudaFuncAttributeMaxDynamicSharedMemorySize, smem_gemm);
    cudaFuncSetAttribute(gemm_packed, cudaFuncAttributeMaxDynamicSharedMemorySize, smem_gemm);

    gemm_qkv<<<dim3(8, 64, 3), 256, smem_gemm>>>(xp, pwq, pwk, pwv, q,
                                                 (uint32_t*)kpp, (uint32_t*)vpp);

    int smem_attn = 196608;   // 192KB
    cudaFuncSetAttribute(attn_tc, cudaFuncAttributeMaxDynamicSharedMemorySize, smem_attn);
    attn_tc<<<dim3(8, 64), 512, smem_attn>>>(q, kpp, vpp, (uint32_t*)ap);

    gemm_packed<<<dim3(8, 64), 256, smem_gemm>>>(ap, pwo, out);
}